// round 12
// baseline (speedup 1.0000x reference)
#include <cuda_runtime.h>
#include <cuda_fp16.h>
#include <cstdint>

#define T_TOK 8192
#define HID   1024
#define NEXP  8
#define INTERN 2816
#define BM 128
#define BK 32                  // k halves per stage
#define NSTG 5
#define MAXTILES 136
#define SLOT_CAP (MAXTILES*BM)
#define PITCH 40               // smem row pitch in halves (80B)

// ---------------- device scratch -------------------------------------------
__device__ int    g_top_idx[T_TOK*2];
__device__ float  g_top_w[T_TOK*2];
__device__ int    g_cnt[NEXP];
__device__ int    g_fill[NEXP];
__device__ int    g_slot_token[SLOT_CAP];
__device__ float  g_slot_w[SLOT_CAP];
__device__ __half g_xh[(size_t)T_TOK*HID];
__device__ __half g_wgT[(size_t)NEXP*INTERN*HID];   // [e][n=I][k=H]
__device__ __half g_wuT[(size_t)NEXP*INTERN*HID];
__device__ __half g_wdT[(size_t)NEXP*HID*INTERN];   // [e][n=H][k=I]
__device__ __half g_interh[(size_t)SLOT_CAP*INTERN];

// ---------------- helpers ----------------------------------------------------
__device__ __forceinline__ void cp16(uint32_t dst, const void* src, int sz){
    asm volatile("cp.async.cg.shared.global [%0], [%1], 16, %2;\n" :: "r"(dst), "l"(src), "r"(sz));
}
#define CP_COMMIT asm volatile("cp.async.commit_group;\n" ::: "memory")
#define CP_WAIT1  asm volatile("cp.async.wait_group 1;\n" ::: "memory")

#define MMA_F16(c,a,b) \
  asm volatile("mma.sync.aligned.m16n8k16.row.col.f32.f16.f16.f32 " \
               "{%0,%1,%2,%3},{%4,%5,%6,%7},{%8,%9},{%0,%1,%2,%3};" \
               : "+f"((c)[0]),"+f"((c)[1]),"+f"((c)[2]),"+f"((c)[3]) \
               : "r"((a)[0]),"r"((a)[1]),"r"((a)[2]),"r"((a)[3]), \
                 "r"((b)[0]),"r"((b)[1]))

#define LDSM4(r, addr) \
  asm volatile("ldmatrix.sync.aligned.m8n8.x4.shared.b16 {%0,%1,%2,%3}, [%4];" \
               : "=r"((r)[0]),"=r"((r)[1]),"=r"((r)[2]),"=r"((r)[3]) : "r"(addr))

__device__ __forceinline__ uint32_t s2u(const void* p){
    uint32_t a;
    asm("{ .reg .u64 t; cvta.to.shared.u64 t, %1; cvt.u32.u64 %0, t; }" : "=r"(a) : "l"(p));
    return a;
}

struct TileInfo { int e, slot0, ebase, ecnt; };
__device__ __forceinline__ TileInfo resolve_tile(int bx){
    TileInfo ti; ti.e = -1; ti.slot0 = 0; ti.ebase = 0; ti.ecnt = 0;
    int tacc = 0, base = 0;
    #pragma unroll
    for (int i=0;i<NEXP;i++){
        int c = g_cnt[i];
        int nt = (c + BM - 1) >> 7;
        if (ti.e < 0 && bx < tacc + nt){
            ti.e = i; ti.slot0 = base + (bx - tacc)*BM; ti.ebase = base; ti.ecnt = c;
        }
        tacc += nt; base += nt*BM;
    }
    return ti;
}

// ---------------- kernel 0: fused pre-pass (+ fused router) --------------------
// z<8: wg transpose, z<16: wu, z<24: wd, z==24: x->fp16 + out zero, z==25: router
__global__ void k_pre(const float* __restrict__ x,  const float* __restrict__ wg,
                      const float* __restrict__ wu, const float* __restrict__ wd,
                      const float* __restrict__ rw, float* __restrict__ out){
    int z = blockIdx.z;
    int tx = threadIdx.x, ty = threadIdx.y;     // 32 x 8
    int tid = ty*32 + tx;
    if (z < 24){
        __shared__ float t[64][33];
        const float* src; __half* dst; int K, N, xt, yt;
        int tl = blockIdx.y*88 + blockIdx.x;    // 0..1407
        if (z < 8){       src = wg + (size_t)z*HID*INTERN;      dst = g_wgT + (size_t)z*INTERN*HID;
                          K = HID; N = INTERN; xt = blockIdx.x; yt = blockIdx.y; }           // 88 x 16
        else if (z < 16){ int e = z-8;  src = wu + (size_t)e*HID*INTERN; dst = g_wuT + (size_t)e*INTERN*HID;
                          K = HID; N = INTERN; xt = blockIdx.x; yt = blockIdx.y; }
        else {            int e = z-16; src = wd + (size_t)e*INTERN*HID; dst = g_wdT + (size_t)e*HID*INTERN;
                          K = INTERN; N = HID;  xt = tl & 31;   yt = tl >> 5; }              // 32 x 44
        int x0 = xt*32, y0 = yt*64;
        #pragma unroll
        for (int j=0;j<8;j++)
            t[ty+8*j][tx] = src[(size_t)(y0+ty+8*j)*N + x0+tx];
        __syncthreads();
        int n = tid>>3, kc = (tid&7)*8;
        __half2 h[4];
        #pragma unroll
        for (int i=0;i<4;i++)
            h[i] = __floats2half2_rn(t[kc+2*i][n], t[kc+2*i+1][n]);
        *(uint4*)(dst + (size_t)(x0+n)*K + y0 + kc) = *(uint4*)h;
    } else if (z == 24){
        int bid = blockIdx.y*gridDim.x + blockIdx.x;
        const int NH2 = T_TOK*HID/2;
        const int STRD = 88*16*256;
        for (int i = bid*256 + tid; i < NH2; i += STRD){
            float2 v = ((const float2*)x)[i];
            ((__half2*)g_xh)[i] = __floats2half2_rn(v.x, v.y);
            ((float2*)out)[i] = make_float2(0.f, 0.f);
        }
    } else {
        // router slice (counters pre-zeroed by memset node)
        int bid = blockIdx.y*gridDim.x + blockIdx.x;    // 0..1407
        int tokw = bid*8 + (tid>>5);
        int lane = tid & 31;
        if (tokw >= T_TOK) return;
        const float* xr = x + (size_t)tokw*HID;
        float acc[NEXP];
        #pragma unroll
        for (int e=0;e<NEXP;e++) acc[e]=0.f;
        for (int j=lane; j<HID; j+=32){
            float v = xr[j];
            const float* r = rw + j*NEXP;
            #pragma unroll
            for (int e=0;e<NEXP;e++) acc[e] += v*r[e];
        }
        #pragma unroll
        for (int o=16;o>0;o>>=1)
            #pragma unroll
            for (int e=0;e<NEXP;e++) acc[e] += __shfl_down_sync(0xffffffffu, acc[e], o);
        if (lane==0){
            int i0=0; float l0=acc[0];
            #pragma unroll
            for (int e=1;e<NEXP;e++) if (acc[e]>l0){ l0=acc[e]; i0=e; }
            int i1=-1; float l1=-1e30f;
            #pragma unroll
            for (int e=0;e<NEXP;e++) if (e!=i0 && acc[e]>l1){ l1=acc[e]; i1=e; }
            float w0 = 1.f/(1.f + expf(l1 - l0));
            g_top_idx[tokw*2+0]=i0; g_top_idx[tokw*2+1]=i1;
            g_top_w[tokw*2+0]=w0;   g_top_w[tokw*2+1]=1.f-w0;
            atomicAdd(&g_cnt[i0],1); atomicAdd(&g_cnt[i1],1);
        }
    }
}

// ---------------- kernel 2: scatter -------------------------------------------
__global__ void k_scatter(){
    int t = blockIdx.x*blockDim.x + threadIdx.x;
    if (t>=T_TOK) return;
    int base[NEXP]; int b=0;
    #pragma unroll
    for (int e=0;e<NEXP;e++){ base[e]=b; b += ((g_cnt[e]+BM-1)>>7)<<7; }
    #pragma unroll
    for (int k=0;k<2;k++){
        int e = g_top_idx[t*2+k];
        int pos = atomicAdd(&g_fill[e],1);
        int slot = base[e]+pos;
        g_slot_token[slot]=t;
        g_slot_w[slot]=g_top_w[t*2+k];
    }
}

// ============ GEMM1: 256 thr, warp 32x(32g+32u), 5-stage, sync per 2 kt =======
#define G1_ASTG (BM*PITCH)                 // 5120 halves
#define G1_BSTG (128*PITCH)                // 5120 halves
#define G1_SMEM ((G1_ASTG+G1_BSTG)*NSTG*2) // 102400 bytes

__global__ void __launch_bounds__(256,2) k_gemm1(){
    extern __shared__ __half smh[];
    TileInfo ti = resolve_tile(blockIdx.x);
    if (ti.e < 0) return;
    int slot0 = ti.slot0;
    int n0 = blockIdx.y*64;
    int tid=threadIdx.x, lane=tid&31, warp=tid>>5;
    int wm = warp>>1, wn = warp&1;
    uint32_t sA = s2u(smh);
    uint32_t sB = sA + NSTG*G1_ASTG*2;

    int lAr = lane & 15,              lAk = 8*(lane>>4);
    int lBr = (lane&7) + 8*(lane>>4), lBk = 8*((lane>>3)&1);

    int arow = tid>>1, ak = (tid&1)*16;
    int vrow = (slot0 + arow - ti.ebase) < ti.ecnt;
    int tok = vrow ? g_slot_token[slot0+arow] : 0;
    const __half* asrc = g_xh + (size_t)tok*HID + ak;
    int asz = vrow ? 16 : 0;
    int brow = tid>>1, bk = (tid&1)*16;
    const __half* bsrc = ((brow<64)? g_wgT + (size_t)ti.e*INTERN*HID + (size_t)(n0+brow)*HID
                                   : g_wuT + (size_t)ti.e*INTERN*HID + (size_t)(n0+brow-64)*HID) + bk;

    float cg[2][4][4], cu[2][4][4];
    #pragma unroll
    for (int i=0;i<2;i++)
        #pragma unroll
        for (int j=0;j<4;j++)
            #pragma unroll
            for (int r=0;r<4;r++){ cg[i][j][r]=0.f; cu[i][j][r]=0.f; }

    auto stage = [&](int s, int k0){
        uint32_t ad = sA + (uint32_t)(s*G1_ASTG + arow*PITCH + ak)*2;
        cp16(ad,      asrc + k0,     asz);
        cp16(ad + 16, asrc + k0 + 8, asz);
        uint32_t bd = sB + (uint32_t)(s*G1_BSTG + brow*PITCH + bk)*2;
        cp16(bd,      bsrc + k0,     16);
        cp16(bd + 16, bsrc + k0 + 8, 16);
        CP_COMMIT;
    };

    stage(0, 0); stage(1, BK); stage(2, 2*BK);
    const int NT = HID/BK;   // 32, even
    for (int j=0; j<NT; j+=2){
        CP_WAIT1;
        __syncthreads();
        int k3 = j+3, k4 = j+4;
        if (k3 < NT) stage(k3%NSTG, k3*BK); else CP_COMMIT;
        if (k4 < NT) stage(k4%NSTG, k4*BK); else CP_COMMIT;
        #pragma unroll
        for (int h=0; h<2; h++){
            int s = (j+h)%NSTG;
            uint32_t aoff = sA + (uint32_t)(s*G1_ASTG)*2;
            uint32_t boff = sB + (uint32_t)(s*G1_BSTG)*2;
            #pragma unroll
            for (int ks=0; ks<2; ks++){
                int kb = ks*16;
                uint32_t a0[4], a1[4];
                LDSM4(a0, aoff + (uint32_t)((wm*32     + lAr)*PITCH + kb + lAk)*2);
                LDSM4(a1, aoff + (uint32_t)((wm*32 +16 + lAr)*PITCH + kb + lAk)*2);
                #pragma unroll
                for (int nq=0;nq<2;nq++){
                    int c0 = wn*32 + nq*16;
                    uint32_t bg[4], bu[4];
                    LDSM4(bg, boff + (uint32_t)((c0    + lBr)*PITCH + kb + lBk)*2);
                    LDSM4(bu, boff + (uint32_t)((c0+64 + lBr)*PITCH + kb + lBk)*2);
                    MMA_F16(cg[0][nq*2+0], a0, bg+0);
                    MMA_F16(cg[0][nq*2+1], a0, bg+2);
                    MMA_F16(cg[1][nq*2+0], a1, bg+0);
                    MMA_F16(cg[1][nq*2+1], a1, bg+2);
                    MMA_F16(cu[0][nq*2+0], a0, bu+0);
                    MMA_F16(cu[0][nq*2+1], a0, bu+2);
                    MMA_F16(cu[1][nq*2+0], a1, bu+0);
                    MMA_F16(cu[1][nq*2+1], a1, bu+2);
                }
            }
        }
    }
    int g8 = lane>>2, tg = lane&3;
    #pragma unroll
    for (int mi=0;mi<2;mi++)
        #pragma unroll
        for (int ni=0;ni<4;ni++)
            #pragma unroll
            for (int rr=0;rr<2;rr++){
                int row = wm*32 + mi*16 + g8 + rr*8;
                int col = wn*32 + ni*8 + 2*tg;
                float g0 = cg[mi][ni][rr*2+0], u0 = cu[mi][ni][rr*2+0];
                float g1 = cg[mi][ni][rr*2+1], u1 = cu[mi][ni][rr*2+1];
                float v0 = u0 * (g0 / (1.f + expf(-g0)));
                float v1 = u1 * (g1 / (1.f + expf(-g1)));
                *(__half2*)(g_interh + (size_t)(slot0+row)*INTERN + n0 + col)
                    = __floats2half2_rn(v0, v1);
            }
}

// ============ GEMM2: grid (n-blocks, tiles) for L2 m-tile reuse ===============
#define G2_ASTG (BM*PITCH)                 // 5120 halves
#define G2_BSTG (128*PITCH)                // 5120 halves
#define G2_SMEM ((G2_ASTG+G2_BSTG)*NSTG*2) // 102400 bytes

__global__ void __launch_bounds__(256,2) k_gemm2(float* __restrict__ out){
    extern __shared__ __half smh[];
    TileInfo ti = resolve_tile(blockIdx.y);          // tile on y (slow axis)
    if (ti.e < 0) return;
    int slot0 = ti.slot0;
    int n0 = blockIdx.x*128;                         // n-block on x (fast axis)
    int tid=threadIdx.x, lane=tid&31, warp=tid>>5;
    int wm = warp>>1, wn = warp&1;
    uint32_t sA = s2u(smh);
    uint32_t sB = sA + NSTG*G2_ASTG*2;

    int lAr = lane & 15,              lAk = 8*(lane>>4);
    int lBr = (lane&7) + 8*(lane>>4), lBk = 8*((lane>>3)&1);

    int arow = tid>>1, ak = (tid&1)*16;
    const __half* asrc = g_interh + (size_t)(slot0+arow)*INTERN + ak;
    int brow = tid>>1, bk = (tid&1)*16;
    const __half* bsrc = g_wdT + (size_t)ti.e*HID*INTERN + (size_t)(n0+brow)*INTERN + bk;

    float cc[2][8][4];
    #pragma unroll
    for (int i=0;i<2;i++)
        #pragma unroll
        for (int j=0;j<8;j++)
            #pragma unroll
            for (int r=0;r<4;r++) cc[i][j][r]=0.f;

    auto stage = [&](int s, int k0){
        uint32_t ad = sA + (uint32_t)(s*G2_ASTG + arow*PITCH + ak)*2;
        cp16(ad,      asrc + k0,     16);
        cp16(ad + 16, asrc + k0 + 8, 16);
        uint32_t bd = sB + (uint32_t)(s*G2_BSTG + brow*PITCH + bk)*2;
        cp16(bd,      bsrc + k0,     16);
        cp16(bd + 16, bsrc + k0 + 8, 16);
        CP_COMMIT;
    };

    stage(0, 0); stage(1, BK); stage(2, 2*BK);
    const int NT = INTERN/BK;   // 88, even
    for (int j=0; j<NT; j+=2){
        CP_WAIT1;
        __syncthreads();
        int k3 = j+3, k4 = j+4;
        if (k3 < NT) stage(k3%NSTG, k3*BK); else CP_COMMIT;
        if (k4 < NT) stage(k4%NSTG, k4*BK); else CP_COMMIT;
        #pragma unroll
        for (int h=0; h<2; h++){
            int s = (j+h)%NSTG;
            uint32_t aoff = sA + (uint32_t)(s*G2_ASTG)*2;
            uint32_t boff = sB + (uint32_t)(s*G2_BSTG)*2;
            #pragma unroll
            for (int ks=0; ks<2; ks++){
                int kb = ks*16;
                uint32_t a0[4], a1[4];
                LDSM4(a0, aoff + (uint32_t)((wm*32     + lAr)*PITCH + kb + lAk)*2);
                LDSM4(a1, aoff + (uint32_t)((wm*32 +16 + lAr)*PITCH + kb + lAk)*2);
                #pragma unroll
                for (int nq=0;nq<4;nq++){
                    int c0 = wn*64 + nq*16;
                    uint32_t bf[4];
                    LDSM4(bf, boff + (uint32_t)((c0 + lBr)*PITCH + kb + lBk)*2);
                    MMA_F16(cc[0][nq*2+0], a0, bf+0);
                    MMA_F16(cc[0][nq*2+1], a0, bf+2);
                    MMA_F16(cc[1][nq*2+0], a1, bf+0);
                    MMA_F16(cc[1][nq*2+1], a1, bf+2);
                }
            }
        }
    }
    // fused combine: out[token] += w_slot * val (2 commutative fp32 adds/elt)
    int g8 = lane>>2, tg = lane&3;
    #pragma unroll
    for (int mi=0;mi<2;mi++){
        #pragma unroll
        for (int rr=0;rr<2;rr++){
            int row = wm*32 + mi*16 + g8 + rr*8;
            if ((slot0 + row - ti.ebase) >= ti.ecnt) continue;
            int tokn = g_slot_token[slot0+row];
            float w  = g_slot_w[slot0+row];
            float* orow = out + (size_t)tokn*HID + n0;
            #pragma unroll
            for (int nj=0;nj<8;nj++){
                int col = wn*64 + (nj>>1)*16 + (nj&1)*8 + 2*tg;
                atomicAdd(orow + col,     w*cc[mi][nj][rr*2+0]);
                atomicAdd(orow + col + 1, w*cc[mi][nj][rr*2+1]);
            }
        }
    }
}

// ---------------- launch -----------------------------------------------------
extern "C" void kernel_launch(void* const* d_in, const int* in_sizes, int n_in,
                              void* d_out, int out_size){
    const float* x  = (const float*)d_in[0];
    const float* rw = (const float*)d_in[1];
    const float* wg = (const float*)d_in[2];
    const float* wu = (const float*)d_in[3];
    const float* wd = (const float*)d_in[4];
    float* out = (float*)d_out;

    cudaFuncSetAttribute(k_gemm1, cudaFuncAttributeMaxDynamicSharedMemorySize, G1_SMEM);
    cudaFuncSetAttribute(k_gemm2, cudaFuncAttributeMaxDynamicSharedMemorySize, G2_SMEM);

    void *cntp, *fillp;
    cudaGetSymbolAddress(&cntp,  g_cnt);
    cudaGetSymbolAddress(&fillp, g_fill);
    cudaMemsetAsync(cntp,  0, NEXP*sizeof(int));
    cudaMemsetAsync(fillp, 0, NEXP*sizeof(int));

    k_pre<<<dim3(88, 16, 26), dim3(32,8)>>>(x, wg, wu, wd, rw, out);
    k_scatter<<<(T_TOK+255)/256, 256>>>();
    k_gemm1<<<dim3(MAXTILES, INTERN/64), 256, G1_SMEM>>>();
    k_gemm2<<<dim3(HID/128, MAXTILES), 256, G2_SMEM>>>(out);
}

// round 13
// speedup vs baseline: 1.0008x; 1.0008x over previous
#include <cuda_runtime.h>
#include <cuda_fp16.h>
#include <cstdint>

#define T_TOK 8192
#define HID   1024
#define NEXP  8
#define INTERN 2816
#define BM 128
#define BK 32                  // k halves per stage
#define NSTG 5
#define MAXTILES 136
#define SLOT_CAP (MAXTILES*BM)
#define PITCH 40               // smem row pitch in halves (80B)

// ---------------- device scratch -------------------------------------------
__device__ int    g_top_idx[T_TOK*2];
__device__ float  g_top_w[T_TOK*2];
__device__ int    g_cnt[NEXP];
__device__ int    g_fill[NEXP];
__device__ int    g_slot_token[SLOT_CAP];
__device__ float  g_slot_w[SLOT_CAP];
__device__ __half g_xh[(size_t)T_TOK*HID];
__device__ __half g_wgT[(size_t)NEXP*INTERN*HID];   // [e][n=I][k=H]
__device__ __half g_wuT[(size_t)NEXP*INTERN*HID];
__device__ __half g_wdT[(size_t)NEXP*HID*INTERN];   // [e][n=H][k=I]
__device__ __half g_interh[(size_t)SLOT_CAP*INTERN];

// ---------------- helpers ----------------------------------------------------
__device__ __forceinline__ void cp16(uint32_t dst, const void* src, int sz){
    asm volatile("cp.async.cg.shared.global [%0], [%1], 16, %2;\n" :: "r"(dst), "l"(src), "r"(sz));
}
#define CP_COMMIT asm volatile("cp.async.commit_group;\n" ::: "memory")
#define CP_WAIT1  asm volatile("cp.async.wait_group 1;\n" ::: "memory")

#define MMA_F16(c,a,b) \
  asm volatile("mma.sync.aligned.m16n8k16.row.col.f32.f16.f16.f32 " \
               "{%0,%1,%2,%3},{%4,%5,%6,%7},{%8,%9},{%0,%1,%2,%3};" \
               : "+f"((c)[0]),"+f"((c)[1]),"+f"((c)[2]),"+f"((c)[3]) \
               : "r"((a)[0]),"r"((a)[1]),"r"((a)[2]),"r"((a)[3]), \
                 "r"((b)[0]),"r"((b)[1]))

#define LDSM4(r, addr) \
  asm volatile("ldmatrix.sync.aligned.m8n8.x4.shared.b16 {%0,%1,%2,%3}, [%4];" \
               : "=r"((r)[0]),"=r"((r)[1]),"=r"((r)[2]),"=r"((r)[3]) : "r"(addr))

__device__ __forceinline__ uint32_t s2u(const void* p){
    uint32_t a;
    asm("{ .reg .u64 t; cvta.to.shared.u64 t, %1; cvt.u32.u64 %0, t; }" : "=r"(a) : "l"(p));
    return a;
}

struct TileInfo { int e, slot0, ebase, ecnt; };
__device__ __forceinline__ TileInfo resolve_tile(int bx){
    TileInfo ti; ti.e = -1; ti.slot0 = 0; ti.ebase = 0; ti.ecnt = 0;
    int tacc = 0, base = 0;
    #pragma unroll
    for (int i=0;i<NEXP;i++){
        int c = g_cnt[i];
        int nt = (c + BM - 1) >> 7;
        if (ti.e < 0 && bx < tacc + nt){
            ti.e = i; ti.slot0 = base + (bx - tacc)*BM; ti.ebase = base; ti.ecnt = c;
        }
        tacc += nt; base += nt*BM;
    }
    return ti;
}

// ---------------- weight transpose kernels (fast 64Kx32N tiles) ---------------
__global__ void k_wgu(const float* __restrict__ wg, const float* __restrict__ wu){
    __shared__ float t[64][33];
    int z = blockIdx.z;   // 0..15
    const size_t HI = (size_t)HID*INTERN;
    const float* src; __half* dst;
    if (z < 8){ src = wg + (size_t)z*HI;     dst = g_wgT + (size_t)z*HI; }
    else      { src = wu + (size_t)(z-8)*HI; dst = g_wuT + (size_t)(z-8)*HI; }
    int x0 = blockIdx.x*32, y0 = blockIdx.y*64;   // n offset (88*32=2816), k offset (16*64=1024)
    int tx = threadIdx.x, ty = threadIdx.y;       // 32 x 8
    int tid = ty*32 + tx;
    #pragma unroll
    for (int j=0;j<8;j++)
        t[ty+8*j][tx] = src[(size_t)(y0+ty+8*j)*INTERN + x0+tx];
    __syncthreads();
    int n = tid>>3, kc = (tid&7)*8;
    __half2 h[4];
    #pragma unroll
    for (int i=0;i<4;i++)
        h[i] = __floats2half2_rn(t[kc+2*i][n], t[kc+2*i+1][n]);
    *(uint4*)(dst + (size_t)(x0+n)*HID + y0 + kc) = *(uint4*)h;
}

__global__ void k_wd(const float* __restrict__ wd){
    __shared__ float t[64][33];
    int e = blockIdx.z;   // 0..7
    const size_t HI = (size_t)HID*INTERN;
    const float* src = wd  + (size_t)e*HI;
    __half* dst      = g_wdT + (size_t)e*HI;
    int tl = blockIdx.y*88 + blockIdx.x;          // 0..1407 = 32 x 44
    int x0 = (tl & 31)*32, y0 = (tl >> 5)*64;     // n offset (32*32=1024), k offset (44*64=2816)
    int tx = threadIdx.x, ty = threadIdx.y;
    int tid = ty*32 + tx;
    #pragma unroll
    for (int j=0;j<8;j++)
        t[ty+8*j][tx] = src[(size_t)(y0+ty+8*j)*HID + x0+tx];
    __syncthreads();
    int n = tid>>3, kc = (tid&7)*8;
    __half2 h[4];
    #pragma unroll
    for (int i=0;i<4;i++)
        h[i] = __floats2half2_rn(t[kc+2*i][n], t[kc+2*i+1][n]);
    *(uint4*)(dst + (size_t)(x0+n)*INTERN + y0 + kc) = *(uint4*)h;
}

// ---------------- x -> fp16 + zero out ----------------------------------------
__global__ void k_x(const float* __restrict__ x, float* __restrict__ out){
    const int NH2 = T_TOK*HID/2;
    for (int i = blockIdx.x*256 + threadIdx.x; i < NH2; i += 2048*256){
        float2 v = ((const float2*)x)[i];
        ((__half2*)g_xh)[i] = __floats2half2_rn(v.x, v.y);
        ((float2*)out)[i] = make_float2(0.f, 0.f);
    }
}

// ---------------- router (exact fp32) -----------------------------------------
__global__ void k_router(const float* __restrict__ x, const float* __restrict__ rw){
    int warp = (blockIdx.x*blockDim.x + threadIdx.x) >> 5;
    int lane = threadIdx.x & 31;
    if (warp >= T_TOK) return;
    const float* xr = x + (size_t)warp*HID;
    float acc[NEXP];
    #pragma unroll
    for (int e=0;e<NEXP;e++) acc[e]=0.f;
    for (int j=lane; j<HID; j+=32){
        float v = xr[j];
        const float* r = rw + j*NEXP;
        #pragma unroll
        for (int e=0;e<NEXP;e++) acc[e] += v*r[e];
    }
    #pragma unroll
    for (int o=16;o>0;o>>=1)
        #pragma unroll
        for (int e=0;e<NEXP;e++) acc[e] += __shfl_down_sync(0xffffffffu, acc[e], o);
    if (lane==0){
        int i0=0; float l0=acc[0];
        #pragma unroll
        for (int e=1;e<NEXP;e++) if (acc[e]>l0){ l0=acc[e]; i0=e; }
        int i1=-1; float l1=-1e30f;
        #pragma unroll
        for (int e=0;e<NEXP;e++) if (e!=i0 && acc[e]>l1){ l1=acc[e]; i1=e; }
        float w0 = 1.f/(1.f + expf(l1 - l0));
        g_top_idx[warp*2+0]=i0; g_top_idx[warp*2+1]=i1;
        g_top_w[warp*2+0]=w0;   g_top_w[warp*2+1]=1.f-w0;
        atomicAdd(&g_cnt[i0],1); atomicAdd(&g_cnt[i1],1);
    }
}

// ---------------- scatter ------------------------------------------------------
__global__ void k_scatter(){
    int t = blockIdx.x*blockDim.x + threadIdx.x;
    if (t>=T_TOK) return;
    int base[NEXP]; int b=0;
    #pragma unroll
    for (int e=0;e<NEXP;e++){ base[e]=b; b += ((g_cnt[e]+BM-1)>>7)<<7; }
    #pragma unroll
    for (int k=0;k<2;k++){
        int e = g_top_idx[t*2+k];
        int pos = atomicAdd(&g_fill[e],1);
        int slot = base[e]+pos;
        g_slot_token[slot]=t;
        g_slot_w[slot]=g_top_w[t*2+k];
    }
}

// ============ GEMM1: 256 thr, warp 32x(32g+32u), 5-stage, sync per 2 kt =======
#define G1_ASTG (BM*PITCH)                 // 5120 halves
#define G1_BSTG (128*PITCH)                // 5120 halves
#define G1_SMEM ((G1_ASTG+G1_BSTG)*NSTG*2) // 102400 bytes

__global__ void __launch_bounds__(256,2) k_gemm1(){
    extern __shared__ __half smh[];
    TileInfo ti = resolve_tile(blockIdx.x);
    if (ti.e < 0) return;
    int slot0 = ti.slot0;
    int n0 = blockIdx.y*64;
    int tid=threadIdx.x, lane=tid&31, warp=tid>>5;
    int wm = warp>>1, wn = warp&1;
    uint32_t sA = s2u(smh);
    uint32_t sB = sA + NSTG*G1_ASTG*2;

    int lAr = lane & 15,              lAk = 8*(lane>>4);
    int lBr = (lane&7) + 8*(lane>>4), lBk = 8*((lane>>3)&1);

    int arow = tid>>1, ak = (tid&1)*16;
    int vrow = (slot0 + arow - ti.ebase) < ti.ecnt;
    int tok = vrow ? g_slot_token[slot0+arow] : 0;
    const __half* asrc = g_xh + (size_t)tok*HID + ak;
    int asz = vrow ? 16 : 0;
    int brow = tid>>1, bk = (tid&1)*16;
    const __half* bsrc = ((brow<64)? g_wgT + (size_t)ti.e*INTERN*HID + (size_t)(n0+brow)*HID
                                   : g_wuT + (size_t)ti.e*INTERN*HID + (size_t)(n0+brow-64)*HID) + bk;

    float cg[2][4][4], cu[2][4][4];
    #pragma unroll
    for (int i=0;i<2;i++)
        #pragma unroll
        for (int j=0;j<4;j++)
            #pragma unroll
            for (int r=0;r<4;r++){ cg[i][j][r]=0.f; cu[i][j][r]=0.f; }

    auto stage = [&](int s, int k0){
        uint32_t ad = sA + (uint32_t)(s*G1_ASTG + arow*PITCH + ak)*2;
        cp16(ad,      asrc + k0,     asz);
        cp16(ad + 16, asrc + k0 + 8, asz);
        uint32_t bd = sB + (uint32_t)(s*G1_BSTG + brow*PITCH + bk)*2;
        cp16(bd,      bsrc + k0,     16);
        cp16(bd + 16, bsrc + k0 + 8, 16);
        CP_COMMIT;
    };

    stage(0, 0); stage(1, BK); stage(2, 2*BK);
    const int NT = HID/BK;   // 32, even
    for (int j=0; j<NT; j+=2){
        CP_WAIT1;
        __syncthreads();
        int k3 = j+3, k4 = j+4;
        if (k3 < NT) stage(k3%NSTG, k3*BK); else CP_COMMIT;
        if (k4 < NT) stage(k4%NSTG, k4*BK); else CP_COMMIT;
        #pragma unroll
        for (int h=0; h<2; h++){
            int s = (j+h)%NSTG;
            uint32_t aoff = sA + (uint32_t)(s*G1_ASTG)*2;
            uint32_t boff = sB + (uint32_t)(s*G1_BSTG)*2;
            #pragma unroll
            for (int ks=0; ks<2; ks++){
                int kb = ks*16;
                uint32_t a0[4], a1[4];
                LDSM4(a0, aoff + (uint32_t)((wm*32     + lAr)*PITCH + kb + lAk)*2);
                LDSM4(a1, aoff + (uint32_t)((wm*32 +16 + lAr)*PITCH + kb + lAk)*2);
                #pragma unroll
                for (int nq=0;nq<2;nq++){
                    int c0 = wn*32 + nq*16;
                    uint32_t bg[4], bu[4];
                    LDSM4(bg, boff + (uint32_t)((c0    + lBr)*PITCH + kb + lBk)*2);
                    LDSM4(bu, boff + (uint32_t)((c0+64 + lBr)*PITCH + kb + lBk)*2);
                    MMA_F16(cg[0][nq*2+0], a0, bg+0);
                    MMA_F16(cg[0][nq*2+1], a0, bg+2);
                    MMA_F16(cg[1][nq*2+0], a1, bg+0);
                    MMA_F16(cg[1][nq*2+1], a1, bg+2);
                    MMA_F16(cu[0][nq*2+0], a0, bu+0);
                    MMA_F16(cu[0][nq*2+1], a0, bu+2);
                    MMA_F16(cu[1][nq*2+0], a1, bu+0);
                    MMA_F16(cu[1][nq*2+1], a1, bu+2);
                }
            }
        }
    }
    int g8 = lane>>2, tg = lane&3;
    #pragma unroll
    for (int mi=0;mi<2;mi++)
        #pragma unroll
        for (int ni=0;ni<4;ni++)
            #pragma unroll
            for (int rr=0;rr<2;rr++){
                int row = wm*32 + mi*16 + g8 + rr*8;
                int col = wn*32 + ni*8 + 2*tg;
                float g0 = cg[mi][ni][rr*2+0], u0 = cu[mi][ni][rr*2+0];
                float g1 = cg[mi][ni][rr*2+1], u1 = cu[mi][ni][rr*2+1];
                float v0 = u0 * (g0 / (1.f + expf(-g0)));
                float v1 = u1 * (g1 / (1.f + expf(-g1)));
                *(__half2*)(g_interh + (size_t)(slot0+row)*INTERN + n0 + col)
                    = __floats2half2_rn(v0, v1);
            }
}

// ============ GEMM2: 256 thr, warp 32x64, 5-stage/2kt, fused combine ==========
#define G2_ASTG (BM*PITCH)                 // 5120 halves
#define G2_BSTG (128*PITCH)                // 5120 halves
#define G2_SMEM ((G2_ASTG+G2_BSTG)*NSTG*2) // 102400 bytes

__global__ void __launch_bounds__(256,2) k_gemm2(float* __restrict__ out){
    extern __shared__ __half smh[];
    TileInfo ti = resolve_tile(blockIdx.x);
    if (ti.e < 0) return;
    int slot0 = ti.slot0;
    int n0 = blockIdx.y*128;
    int tid=threadIdx.x, lane=tid&31, warp=tid>>5;
    int wm = warp>>1, wn = warp&1;
    uint32_t sA = s2u(smh);
    uint32_t sB = sA + NSTG*G2_ASTG*2;

    int lAr = lane & 15,              lAk = 8*(lane>>4);
    int lBr = (lane&7) + 8*(lane>>4), lBk = 8*((lane>>3)&1);

    int arow = tid>>1, ak = (tid&1)*16;
    const __half* asrc = g_interh + (size_t)(slot0+arow)*INTERN + ak;
    int brow = tid>>1, bk = (tid&1)*16;
    const __half* bsrc = g_wdT + (size_t)ti.e*HID*INTERN + (size_t)(n0+brow)*INTERN + bk;

    float cc[2][8][4];
    #pragma unroll
    for (int i=0;i<2;i++)
        #pragma unroll
        for (int j=0;j<8;j++)
            #pragma unroll
            for (int r=0;r<4;r++) cc[i][j][r]=0.f;

    auto stage = [&](int s, int k0){
        uint32_t ad = sA + (uint32_t)(s*G2_ASTG + arow*PITCH + ak)*2;
        cp16(ad,      asrc + k0,     16);
        cp16(ad + 16, asrc + k0 + 8, 16);
        uint32_t bd = sB + (uint32_t)(s*G2_BSTG + brow*PITCH + bk)*2;
        cp16(bd,      bsrc + k0,     16);
        cp16(bd + 16, bsrc + k0 + 8, 16);
        CP_COMMIT;
    };

    stage(0, 0); stage(1, BK); stage(2, 2*BK);
    const int NT = INTERN/BK;   // 88, even
    for (int j=0; j<NT; j+=2){
        CP_WAIT1;
        __syncthreads();
        int k3 = j+3, k4 = j+4;
        if (k3 < NT) stage(k3%NSTG, k3*BK); else CP_COMMIT;
        if (k4 < NT) stage(k4%NSTG, k4*BK); else CP_COMMIT;
        #pragma unroll
        for (int h=0; h<2; h++){
            int s = (j+h)%NSTG;
            uint32_t aoff = sA + (uint32_t)(s*G2_ASTG)*2;
            uint32_t boff = sB + (uint32_t)(s*G2_BSTG)*2;
            #pragma unroll
            for (int ks=0; ks<2; ks++){
                int kb = ks*16;
                uint32_t a0[4], a1[4];
                LDSM4(a0, aoff + (uint32_t)((wm*32     + lAr)*PITCH + kb + lAk)*2);
                LDSM4(a1, aoff + (uint32_t)((wm*32 +16 + lAr)*PITCH + kb + lAk)*2);
                #pragma unroll
                for (int nq=0;nq<4;nq++){
                    int c0 = wn*64 + nq*16;
                    uint32_t bf[4];
                    LDSM4(bf, boff + (uint32_t)((c0 + lBr)*PITCH + kb + lBk)*2);
                    MMA_F16(cc[0][nq*2+0], a0, bf+0);
                    MMA_F16(cc[0][nq*2+1], a0, bf+2);
                    MMA_F16(cc[1][nq*2+0], a1, bf+0);
                    MMA_F16(cc[1][nq*2+1], a1, bf+2);
                }
            }
        }
    }
    // fused combine: out[token] += w_slot * val (2 commutative fp32 adds/elt)
    int g8 = lane>>2, tg = lane&3;
    #pragma unroll
    for (int mi=0;mi<2;mi++){
        #pragma unroll
        for (int rr=0;rr<2;rr++){
            int row = wm*32 + mi*16 + g8 + rr*8;
            if ((slot0 + row - ti.ebase) >= ti.ecnt) continue;
            int tokn = g_slot_token[slot0+row];
            float w  = g_slot_w[slot0+row];
            float* orow = out + (size_t)tokn*HID + n0;
            #pragma unroll
            for (int nj=0;nj<8;nj++){
                int col = wn*64 + (nj>>1)*16 + (nj&1)*8 + 2*tg;
                atomicAdd(orow + col,     w*cc[mi][nj][rr*2+0]);
                atomicAdd(orow + col + 1, w*cc[mi][nj][rr*2+1]);
            }
        }
    }
}

// ---------------- launch -----------------------------------------------------
extern "C" void kernel_launch(void* const* d_in, const int* in_sizes, int n_in,
                              void* d_out, int out_size){
    const float* x  = (const float*)d_in[0];
    const float* rw = (const float*)d_in[1];
    const float* wg = (const float*)d_in[2];
    const float* wu = (const float*)d_in[3];
    const float* wd = (const float*)d_in[4];
    float* out = (float*)d_out;

    static cudaStream_t s2 = nullptr, s3 = nullptr;
    static cudaEvent_t evR = nullptr, evW = nullptr, evD = nullptr;
    if (!s2){
        cudaStreamCreateWithFlags(&s2, cudaStreamNonBlocking);
        cudaStreamCreateWithFlags(&s3, cudaStreamNonBlocking);
        cudaEventCreateWithFlags(&evR, cudaEventDisableTiming);
        cudaEventCreateWithFlags(&evW, cudaEventDisableTiming);
        cudaEventCreateWithFlags(&evD, cudaEventDisableTiming);
        cudaFuncSetAttribute(k_gemm1, cudaFuncAttributeMaxDynamicSharedMemorySize, G1_SMEM);
        cudaFuncSetAttribute(k_gemm2, cudaFuncAttributeMaxDynamicSharedMemorySize, G2_SMEM);
    }

    void *cntp, *fillp;
    cudaGetSymbolAddress(&cntp,  g_cnt);
    cudaGetSymbolAddress(&fillp, g_fill);
    cudaMemsetAsync(cntp,  0, NEXP*sizeof(int), 0);
    cudaMemsetAsync(fillp, 0, NEXP*sizeof(int), 0);

    // fork: weight conversions on side streams
    cudaEventRecord(evR, 0);
    cudaStreamWaitEvent(s2, evR, 0);
    cudaStreamWaitEvent(s3, evR, 0);
    k_wgu<<<dim3(88, 16, 16), dim3(32,8), 0, s2>>>(wg, wu);
    cudaEventRecord(evW, s2);
    k_wd<<<dim3(88, 16, 8), dim3(32,8), 0, s3>>>(wd);
    cudaEventRecord(evD, s3);

    // main stream: routing chain (concurrent with weight conversion)
    k_x<<<2048, 256>>>(x, out);
    k_router<<<T_TOK/8, 256>>>(x, rw);
    k_scatter<<<(T_TOK+255)/256, 256>>>();

    // join: gemm1 needs wg/wu; gemm2 additionally needs wd
    cudaStreamWaitEvent(0, evW, 0);
    k_gemm1<<<dim3(MAXTILES, INTERN/64), 256, G1_SMEM>>>();
    cudaStreamWaitEvent(0, evD, 0);
    k_gemm2<<<dim3(MAXTILES, HID/128), 256, G2_SMEM>>>(out);
}

// round 14
// speedup vs baseline: 1.0425x; 1.0416x over previous
#include <cuda_runtime.h>
#include <cuda_fp16.h>
#include <cstdint>

#define T_TOK 8192
#define HID   1024
#define NEXP  8
#define INTERN 2816
#define BM 128
#define BK 32                  // k halves per stage
#define NSTG 5
#define MAXTILES 136
#define SLOT_CAP (MAXTILES*BM)
#define PITCH 40               // smem row pitch in halves (80B)

// ---------------- device scratch -------------------------------------------
__device__ int    g_top_idx[T_TOK*2];
__device__ float  g_top_w[T_TOK*2];
__device__ int    g_cnt[NEXP];
__device__ int    g_fill[NEXP];
__device__ int    g_slot_token[SLOT_CAP];
__device__ float  g_slot_w[SLOT_CAP];
__device__ __half g_xh[(size_t)T_TOK*HID];
__device__ __half g_wgT[(size_t)NEXP*INTERN*HID];   // [e][n=I][k=H]
__device__ __half g_wuT[(size_t)NEXP*INTERN*HID];
__device__ __half g_wdT[(size_t)NEXP*HID*INTERN];   // [e][n=H][k=I]
__device__ __half g_interh[(size_t)SLOT_CAP*INTERN];

// ---------------- helpers ----------------------------------------------------
__device__ __forceinline__ void cp16(uint32_t dst, const void* src, int sz){
    asm volatile("cp.async.cg.shared.global [%0], [%1], 16, %2;\n" :: "r"(dst), "l"(src), "r"(sz));
}
#define CP_COMMIT asm volatile("cp.async.commit_group;\n" ::: "memory")
#define CP_WAIT1  asm volatile("cp.async.wait_group 1;\n" ::: "memory")

#define MMA_F16(c,a,b) \
  asm volatile("mma.sync.aligned.m16n8k16.row.col.f32.f16.f16.f32 " \
               "{%0,%1,%2,%3},{%4,%5,%6,%7},{%8,%9},{%0,%1,%2,%3};" \
               : "+f"((c)[0]),"+f"((c)[1]),"+f"((c)[2]),"+f"((c)[3]) \
               : "r"((a)[0]),"r"((a)[1]),"r"((a)[2]),"r"((a)[3]), \
                 "r"((b)[0]),"r"((b)[1]))

#define LDSM4(r, addr) \
  asm volatile("ldmatrix.sync.aligned.m8n8.x4.shared.b16 {%0,%1,%2,%3}, [%4];" \
               : "=r"((r)[0]),"=r"((r)[1]),"=r"((r)[2]),"=r"((r)[3]) : "r"(addr))

__device__ __forceinline__ uint32_t s2u(const void* p){
    uint32_t a;
    asm("{ .reg .u64 t; cvta.to.shared.u64 t, %1; cvt.u32.u64 %0, t; }" : "=r"(a) : "l"(p));
    return a;
}

struct TileInfo { int e, slot0, ebase, ecnt; };
__device__ __forceinline__ TileInfo resolve_tile(int bx){
    TileInfo ti; ti.e = -1; ti.slot0 = 0; ti.ebase = 0; ti.ecnt = 0;
    int tacc = 0, base = 0;
    #pragma unroll
    for (int i=0;i<NEXP;i++){
        int c = g_cnt[i];
        int nt = (c + BM - 1) >> 7;
        if (ti.e < 0 && bx < tacc + nt){
            ti.e = i; ti.slot0 = base + (bx - tacc)*BM; ti.ebase = base; ti.ecnt = c;
        }
        tacc += nt; base += nt*BM;
    }
    return ti;
}

// ---------------- weight transpose kernels (fast 64Kx32N tiles) ---------------
__global__ void k_wgu(const float* __restrict__ wg, const float* __restrict__ wu){
    __shared__ float t[64][33];
    int z = blockIdx.z;   // 0..15
    const size_t HI = (size_t)HID*INTERN;
    const float* src; __half* dst;
    if (z < 8){ src = wg + (size_t)z*HI;     dst = g_wgT + (size_t)z*HI; }
    else      { src = wu + (size_t)(z-8)*HI; dst = g_wuT + (size_t)(z-8)*HI; }
    int x0 = blockIdx.x*32, y0 = blockIdx.y*64;
    int tx = threadIdx.x, ty = threadIdx.y;       // 32 x 8
    int tid = ty*32 + tx;
    #pragma unroll
    for (int j=0;j<8;j++)
        t[ty+8*j][tx] = src[(size_t)(y0+ty+8*j)*INTERN + x0+tx];
    __syncthreads();
    int n = tid>>3, kc = (tid&7)*8;
    __half2 h[4];
    #pragma unroll
    for (int i=0;i<4;i++)
        h[i] = __floats2half2_rn(t[kc+2*i][n], t[kc+2*i+1][n]);
    *(uint4*)(dst + (size_t)(x0+n)*HID + y0 + kc) = *(uint4*)h;
}

__global__ void k_wd(const float* __restrict__ wd){
    __shared__ float t[64][33];
    int e = blockIdx.z;   // 0..7
    const size_t HI = (size_t)HID*INTERN;
    const float* src = wd  + (size_t)e*HI;
    __half* dst      = g_wdT + (size_t)e*HI;
    int tl = blockIdx.y*88 + blockIdx.x;          // 0..1407 = 32 x 44
    int x0 = (tl & 31)*32, y0 = (tl >> 5)*64;
    int tx = threadIdx.x, ty = threadIdx.y;
    int tid = ty*32 + tx;
    #pragma unroll
    for (int j=0;j<8;j++)
        t[ty+8*j][tx] = src[(size_t)(y0+ty+8*j)*HID + x0+tx];
    __syncthreads();
    int n = tid>>3, kc = (tid&7)*8;
    __half2 h[4];
    #pragma unroll
    for (int i=0;i<4;i++)
        h[i] = __floats2half2_rn(t[kc+2*i][n], t[kc+2*i+1][n]);
    *(uint4*)(dst + (size_t)(x0+n)*INTERN + y0 + kc) = *(uint4*)h;
}

// ---------------- x -> fp16 + zero out ----------------------------------------
__global__ void k_x(const float* __restrict__ x, float* __restrict__ out){
    const int NH2 = T_TOK*HID/2;
    for (int i = blockIdx.x*256 + threadIdx.x; i < NH2; i += 2048*256){
        float2 v = ((const float2*)x)[i];
        ((__half2*)g_xh)[i] = __floats2half2_rn(v.x, v.y);
        ((float2*)out)[i] = make_float2(0.f, 0.f);
    }
}

// ---------------- router: rw in smem (pitch 12 -> conflict-free LDS.128) ------
#define RWP 12
__global__ void __launch_bounds__(256) k_router(const float* __restrict__ x,
                                                const float* __restrict__ rw){
    __shared__ float srw[HID*RWP];    // 48KB
    int tid = threadIdx.x;
    for (int idx = tid; idx < HID*NEXP; idx += 256)
        srw[(idx>>3)*RWP + (idx&7)] = rw[idx];
    __syncthreads();
    int warp = tid>>5, lane = tid&31;
    int tok = blockIdx.x*8 + warp;
    const float* xr = x + (size_t)tok*HID;
    float a0=0,a1=0,a2=0,a3=0,a4=0,a5=0,a6=0,a7=0;
    #pragma unroll 4
    for (int j=lane; j<HID; j+=32){
        float v = xr[j];
        const float4* r4 = (const float4*)&srw[j*RWP];
        float4 r0 = r4[0], r1 = r4[1];
        a0 += v*r0.x; a1 += v*r0.y; a2 += v*r0.z; a3 += v*r0.w;
        a4 += v*r1.x; a5 += v*r1.y; a6 += v*r1.z; a7 += v*r1.w;
    }
    float acc[NEXP] = {a0,a1,a2,a3,a4,a5,a6,a7};
    #pragma unroll
    for (int o=16;o>0;o>>=1)
        #pragma unroll
        for (int e=0;e<NEXP;e++) acc[e] += __shfl_down_sync(0xffffffffu, acc[e], o);
    if (lane==0){
        int i0=0; float l0=acc[0];
        #pragma unroll
        for (int e=1;e<NEXP;e++) if (acc[e]>l0){ l0=acc[e]; i0=e; }
        int i1=-1; float l1=-1e30f;
        #pragma unroll
        for (int e=0;e<NEXP;e++) if (e!=i0 && acc[e]>l1){ l1=acc[e]; i1=e; }
        float w0 = 1.f/(1.f + expf(l1 - l0));
        g_top_idx[tok*2+0]=i0; g_top_idx[tok*2+1]=i1;
        g_top_w[tok*2+0]=w0;   g_top_w[tok*2+1]=1.f-w0;
        atomicAdd(&g_cnt[i0],1); atomicAdd(&g_cnt[i1],1);
    }
}

// ---------------- scatter ------------------------------------------------------
__global__ void k_scatter(){
    int t = blockIdx.x*blockDim.x + threadIdx.x;
    if (t>=T_TOK) return;
    int base[NEXP]; int b=0;
    #pragma unroll
    for (int e=0;e<NEXP;e++){ base[e]=b; b += ((g_cnt[e]+BM-1)>>7)<<7; }
    #pragma unroll
    for (int k=0;k<2;k++){
        int e = g_top_idx[t*2+k];
        int pos = atomicAdd(&g_fill[e],1);
        int slot = base[e]+pos;
        g_slot_token[slot]=t;
        g_slot_w[slot]=g_top_w[t*2+k];
    }
}

// ============ GEMM1: 256 thr, warp 32x(32g+32u), 5-stage, sync per 2 kt =======
#define G1_ASTG (BM*PITCH)                 // 5120 halves
#define G1_BSTG (128*PITCH)                // 5120 halves
#define G1_SMEM ((G1_ASTG+G1_BSTG)*NSTG*2) // 102400 bytes

__global__ void __launch_bounds__(256,2) k_gemm1(){
    extern __shared__ __half smh[];
    TileInfo ti = resolve_tile(blockIdx.x);
    if (ti.e < 0) return;
    int slot0 = ti.slot0;
    int n0 = blockIdx.y*64;
    int tid=threadIdx.x, lane=tid&31, warp=tid>>5;
    int wm = warp>>1, wn = warp&1;
    uint32_t sA = s2u(smh);
    uint32_t sB = sA + NSTG*G1_ASTG*2;

    int lAr = lane & 15,              lAk = 8*(lane>>4);
    int lBr = (lane&7) + 8*(lane>>4), lBk = 8*((lane>>3)&1);

    int arow = tid>>1, ak = (tid&1)*16;
    int vrow = (slot0 + arow - ti.ebase) < ti.ecnt;
    int tok = vrow ? g_slot_token[slot0+arow] : 0;
    const __half* asrc = g_xh + (size_t)tok*HID + ak;
    int asz = vrow ? 16 : 0;
    int brow = tid>>1, bk = (tid&1)*16;
    const __half* bsrc = ((brow<64)? g_wgT + (size_t)ti.e*INTERN*HID + (size_t)(n0+brow)*HID
                                   : g_wuT + (size_t)ti.e*INTERN*HID + (size_t)(n0+brow-64)*HID) + bk;

    float cg[2][4][4], cu[2][4][4];
    #pragma unroll
    for (int i=0;i<2;i++)
        #pragma unroll
        for (int j=0;j<4;j++)
            #pragma unroll
            for (int r=0;r<4;r++){ cg[i][j][r]=0.f; cu[i][j][r]=0.f; }

    auto stage = [&](int s, int k0){
        uint32_t ad = sA + (uint32_t)(s*G1_ASTG + arow*PITCH + ak)*2;
        cp16(ad,      asrc + k0,     asz);
        cp16(ad + 16, asrc + k0 + 8, asz);
        uint32_t bd = sB + (uint32_t)(s*G1_BSTG + brow*PITCH + bk)*2;
        cp16(bd,      bsrc + k0,     16);
        cp16(bd + 16, bsrc + k0 + 8, 16);
        CP_COMMIT;
    };

    stage(0, 0); stage(1, BK); stage(2, 2*BK);
    const int NT = HID/BK;   // 32, even
    for (int j=0; j<NT; j+=2){
        CP_WAIT1;
        __syncthreads();
        int k3 = j+3, k4 = j+4;
        if (k3 < NT) stage(k3%NSTG, k3*BK); else CP_COMMIT;
        if (k4 < NT) stage(k4%NSTG, k4*BK); else CP_COMMIT;
        #pragma unroll
        for (int h=0; h<2; h++){
            int s = (j+h)%NSTG;
            uint32_t aoff = sA + (uint32_t)(s*G1_ASTG)*2;
            uint32_t boff = sB + (uint32_t)(s*G1_BSTG)*2;
            #pragma unroll
            for (int ks=0; ks<2; ks++){
                int kb = ks*16;
                uint32_t a0[4], a1[4];
                LDSM4(a0, aoff + (uint32_t)((wm*32     + lAr)*PITCH + kb + lAk)*2);
                LDSM4(a1, aoff + (uint32_t)((wm*32 +16 + lAr)*PITCH + kb + lAk)*2);
                #pragma unroll
                for (int nq=0;nq<2;nq++){
                    int c0 = wn*32 + nq*16;
                    uint32_t bg[4], bu[4];
                    LDSM4(bg, boff + (uint32_t)((c0    + lBr)*PITCH + kb + lBk)*2);
                    LDSM4(bu, boff + (uint32_t)((c0+64 + lBr)*PITCH + kb + lBk)*2);
                    MMA_F16(cg[0][nq*2+0], a0, bg+0);
                    MMA_F16(cg[0][nq*2+1], a0, bg+2);
                    MMA_F16(cg[1][nq*2+0], a1, bg+0);
                    MMA_F16(cg[1][nq*2+1], a1, bg+2);
                    MMA_F16(cu[0][nq*2+0], a0, bu+0);
                    MMA_F16(cu[0][nq*2+1], a0, bu+2);
                    MMA_F16(cu[1][nq*2+0], a1, bu+0);
                    MMA_F16(cu[1][nq*2+1], a1, bu+2);
                }
            }
        }
    }
    int g8 = lane>>2, tg = lane&3;
    #pragma unroll
    for (int mi=0;mi<2;mi++)
        #pragma unroll
        for (int ni=0;ni<4;ni++)
            #pragma unroll
            for (int rr=0;rr<2;rr++){
                int row = wm*32 + mi*16 + g8 + rr*8;
                int col = wn*32 + ni*8 + 2*tg;
                float g0 = cg[mi][ni][rr*2+0], u0 = cu[mi][ni][rr*2+0];
                float g1 = cg[mi][ni][rr*2+1], u1 = cu[mi][ni][rr*2+1];
                float v0 = u0 * (g0 / (1.f + expf(-g0)));
                float v1 = u1 * (g1 / (1.f + expf(-g1)));
                *(__half2*)(g_interh + (size_t)(slot0+row)*INTERN + n0 + col)
                    = __floats2half2_rn(v0, v1);
            }
}

// ============ GEMM2: 256 thr, warp 32x64, 5-stage/2kt, fused combine ==========
#define G2_ASTG (BM*PITCH)                 // 5120 halves
#define G2_BSTG (128*PITCH)                // 5120 halves
#define G2_SMEM ((G2_ASTG+G2_BSTG)*NSTG*2) // 102400 bytes

__global__ void __launch_bounds__(256,2) k_gemm2(float* __restrict__ out){
    extern __shared__ __half smh[];
    TileInfo ti = resolve_tile(blockIdx.x);
    if (ti.e < 0) return;
    int slot0 = ti.slot0;
    int n0 = blockIdx.y*128;
    int tid=threadIdx.x, lane=tid&31, warp=tid>>5;
    int wm = warp>>1, wn = warp&1;
    uint32_t sA = s2u(smh);
    uint32_t sB = sA + NSTG*G2_ASTG*2;

    int lAr = lane & 15,              lAk = 8*(lane>>4);
    int lBr = (lane&7) + 8*(lane>>4), lBk = 8*((lane>>3)&1);

    int arow = tid>>1, ak = (tid&1)*16;
    const __half* asrc = g_interh + (size_t)(slot0+arow)*INTERN + ak;
    int brow = tid>>1, bk = (tid&1)*16;
    const __half* bsrc = g_wdT + (size_t)ti.e*HID*INTERN + (size_t)(n0+brow)*INTERN + bk;

    float cc[2][8][4];
    #pragma unroll
    for (int i=0;i<2;i++)
        #pragma unroll
        for (int j=0;j<8;j++)
            #pragma unroll
            for (int r=0;r<4;r++) cc[i][j][r]=0.f;

    auto stage = [&](int s, int k0){
        uint32_t ad = sA + (uint32_t)(s*G2_ASTG + arow*PITCH + ak)*2;
        cp16(ad,      asrc + k0,     16);
        cp16(ad + 16, asrc + k0 + 8, 16);
        uint32_t bd = sB + (uint32_t)(s*G2_BSTG + brow*PITCH + bk)*2;
        cp16(bd,      bsrc + k0,     16);
        cp16(bd + 16, bsrc + k0 + 8, 16);
        CP_COMMIT;
    };

    stage(0, 0); stage(1, BK); stage(2, 2*BK);
    const int NT = INTERN/BK;   // 88, even
    for (int j=0; j<NT; j+=2){
        CP_WAIT1;
        __syncthreads();
        int k3 = j+3, k4 = j+4;
        if (k3 < NT) stage(k3%NSTG, k3*BK); else CP_COMMIT;
        if (k4 < NT) stage(k4%NSTG, k4*BK); else CP_COMMIT;
        #pragma unroll
        for (int h=0; h<2; h++){
            int s = (j+h)%NSTG;
            uint32_t aoff = sA + (uint32_t)(s*G2_ASTG)*2;
            uint32_t boff = sB + (uint32_t)(s*G2_BSTG)*2;
            #pragma unroll
            for (int ks=0; ks<2; ks++){
                int kb = ks*16;
                uint32_t a0[4], a1[4];
                LDSM4(a0, aoff + (uint32_t)((wm*32     + lAr)*PITCH + kb + lAk)*2);
                LDSM4(a1, aoff + (uint32_t)((wm*32 +16 + lAr)*PITCH + kb + lAk)*2);
                #pragma unroll
                for (int nq=0;nq<4;nq++){
                    int c0 = wn*64 + nq*16;
                    uint32_t bf[4];
                    LDSM4(bf, boff + (uint32_t)((c0 + lBr)*PITCH + kb + lBk)*2);
                    MMA_F16(cc[0][nq*2+0], a0, bf+0);
                    MMA_F16(cc[0][nq*2+1], a0, bf+2);
                    MMA_F16(cc[1][nq*2+0], a1, bf+0);
                    MMA_F16(cc[1][nq*2+1], a1, bf+2);
                }
            }
        }
    }
    // fused combine: out[token] += w_slot * val (2 commutative fp32 adds/elt)
    int g8 = lane>>2, tg = lane&3;
    #pragma unroll
    for (int mi=0;mi<2;mi++){
        #pragma unroll
        for (int rr=0;rr<2;rr++){
            int row = wm*32 + mi*16 + g8 + rr*8;
            if ((slot0 + row - ti.ebase) >= ti.ecnt) continue;
            int tokn = g_slot_token[slot0+row];
            float w  = g_slot_w[slot0+row];
            float* orow = out + (size_t)tokn*HID + n0;
            #pragma unroll
            for (int nj=0;nj<8;nj++){
                int col = wn*64 + (nj>>1)*16 + (nj&1)*8 + 2*tg;
                atomicAdd(orow + col,     w*cc[mi][nj][rr*2+0]);
                atomicAdd(orow + col + 1, w*cc[mi][nj][rr*2+1]);
            }
        }
    }
}

// ---------------- launch -----------------------------------------------------
extern "C" void kernel_launch(void* const* d_in, const int* in_sizes, int n_in,
                              void* d_out, int out_size){
    const float* x  = (const float*)d_in[0];
    const float* rw = (const float*)d_in[1];
    const float* wg = (const float*)d_in[2];
    const float* wu = (const float*)d_in[3];
    const float* wd = (const float*)d_in[4];
    float* out = (float*)d_out;

    static cudaStream_t s2 = nullptr, s3 = nullptr;
    static cudaEvent_t evR = nullptr, evW = nullptr, evD = nullptr;
    if (!s2){
        cudaStreamCreateWithFlags(&s2, cudaStreamNonBlocking);
        cudaStreamCreateWithFlags(&s3, cudaStreamNonBlocking);
        cudaEventCreateWithFlags(&evR, cudaEventDisableTiming);
        cudaEventCreateWithFlags(&evW, cudaEventDisableTiming);
        cudaEventCreateWithFlags(&evD, cudaEventDisableTiming);
        cudaFuncSetAttribute(k_gemm1, cudaFuncAttributeMaxDynamicSharedMemorySize, G1_SMEM);
        cudaFuncSetAttribute(k_gemm2, cudaFuncAttributeMaxDynamicSharedMemorySize, G2_SMEM);
    }

    void *cntp, *fillp;
    cudaGetSymbolAddress(&cntp,  g_cnt);
    cudaGetSymbolAddress(&fillp, g_fill);
    cudaMemsetAsync(cntp,  0, NEXP*sizeof(int), 0);
    cudaMemsetAsync(fillp, 0, NEXP*sizeof(int), 0);

    // fork: weight conversions on side streams
    cudaEventRecord(evR, 0);
    cudaStreamWaitEvent(s2, evR, 0);
    cudaStreamWaitEvent(s3, evR, 0);
    k_wgu<<<dim3(88, 16, 16), dim3(32,8), 0, s2>>>(wg, wu);
    cudaEventRecord(evW, s2);
    k_wd<<<dim3(88, 16, 8), dim3(32,8), 0, s3>>>(wd);
    cudaEventRecord(evD, s3);

    // main stream: routing chain (concurrent with weight conversion)
    k_x<<<2048, 256>>>(x, out);
    k_router<<<T_TOK/8, 256>>>(x, rw);
    k_scatter<<<(T_TOK+255)/256, 256>>>();

    // join: gemm1 needs wg/wu; gemm2 additionally needs wd
    cudaStreamWaitEvent(0, evW, 0);
    k_gemm1<<<dim3(MAXTILES, INTERN/64), 256, G1_SMEM>>>();
    cudaStreamWaitEvent(0, evD, 0);
    k_gemm2<<<dim3(MAXTILES, HID/128), 256, G2_SMEM>>>(out);
}

// round 15
// speedup vs baseline: 1.0472x; 1.0045x over previous
#include <cuda_runtime.h>
#include <cuda_fp16.h>
#include <cstdint>

#define T_TOK 8192
#define HID   1024
#define NEXP  8
#define INTERN 2816
#define BM 128
#define BK 32                  // k halves per stage
#define NSTG 5
#define MAXTILES 136
#define SLOT_CAP (MAXTILES*BM)
#define PITCH 40               // smem row pitch in halves (80B)

// ---------------- device scratch -------------------------------------------
__device__ int    g_top_idx[T_TOK*2];
__device__ float  g_top_w[T_TOK*2];
__device__ int    g_cnt[NEXP];
__device__ int    g_fill[NEXP];
__device__ int    g_slot_token[SLOT_CAP];
__device__ float  g_slot_w[SLOT_CAP];
__device__ __half g_xh[(size_t)T_TOK*HID];
__device__ __half g_wgT[(size_t)NEXP*INTERN*HID];   // [e][n=I][k=H]
__device__ __half g_wuT[(size_t)NEXP*INTERN*HID];
__device__ __half g_wdT[(size_t)NEXP*HID*INTERN];   // [e][n=H][k=I]
__device__ __half g_interh[(size_t)SLOT_CAP*INTERN];

// ---------------- helpers ----------------------------------------------------
__device__ __forceinline__ void cp16(uint32_t dst, const void* src, int sz){
    asm volatile("cp.async.cg.shared.global [%0], [%1], 16, %2;\n" :: "r"(dst), "l"(src), "r"(sz));
}
#define CP_COMMIT asm volatile("cp.async.commit_group;\n" ::: "memory")
#define CP_WAIT1  asm volatile("cp.async.wait_group 1;\n" ::: "memory")

#define MMA_F16(c,a,b) \
  asm volatile("mma.sync.aligned.m16n8k16.row.col.f32.f16.f16.f32 " \
               "{%0,%1,%2,%3},{%4,%5,%6,%7},{%8,%9},{%0,%1,%2,%3};" \
               : "+f"((c)[0]),"+f"((c)[1]),"+f"((c)[2]),"+f"((c)[3]) \
               : "r"((a)[0]),"r"((a)[1]),"r"((a)[2]),"r"((a)[3]), \
                 "r"((b)[0]),"r"((b)[1]))

#define LDSM4(r, addr) \
  asm volatile("ldmatrix.sync.aligned.m8n8.x4.shared.b16 {%0,%1,%2,%3}, [%4];" \
               : "=r"((r)[0]),"=r"((r)[1]),"=r"((r)[2]),"=r"((r)[3]) : "r"(addr))

__device__ __forceinline__ uint32_t s2u(const void* p){
    uint32_t a;
    asm("{ .reg .u64 t; cvta.to.shared.u64 t, %1; cvt.u32.u64 %0, t; }" : "=r"(a) : "l"(p));
    return a;
}

struct TileInfo { int e, slot0, ebase, ecnt; };
__device__ __forceinline__ TileInfo resolve_tile(int bx){
    TileInfo ti; ti.e = -1; ti.slot0 = 0; ti.ebase = 0; ti.ecnt = 0;
    int tacc = 0, base = 0;
    #pragma unroll
    for (int i=0;i<NEXP;i++){
        int c = g_cnt[i];
        int nt = (c + BM - 1) >> 7;
        if (ti.e < 0 && bx < tacc + nt){
            ti.e = i; ti.slot0 = base + (bx - tacc)*BM; ti.ebase = base; ti.ecnt = c;
        }
        tacc += nt; base += nt*BM;
    }
    return ti;
}

// ---------------- weight transpose kernels (fast 64Kx32N tiles) ---------------
__global__ void k_wgu(const float* __restrict__ wg, const float* __restrict__ wu){
    __shared__ float t[64][33];
    int z = blockIdx.z;   // 0..15
    const size_t HI = (size_t)HID*INTERN;
    const float* src; __half* dst;
    if (z < 8){ src = wg + (size_t)z*HI;     dst = g_wgT + (size_t)z*HI; }
    else      { src = wu + (size_t)(z-8)*HI; dst = g_wuT + (size_t)(z-8)*HI; }
    int x0 = blockIdx.x*32, y0 = blockIdx.y*64;
    int tx = threadIdx.x, ty = threadIdx.y;       // 32 x 8
    int tid = ty*32 + tx;
    #pragma unroll
    for (int j=0;j<8;j++)
        t[ty+8*j][tx] = src[(size_t)(y0+ty+8*j)*INTERN + x0+tx];
    __syncthreads();
    int n = tid>>3, kc = (tid&7)*8;
    __half2 h[4];
    #pragma unroll
    for (int i=0;i<4;i++)
        h[i] = __floats2half2_rn(t[kc+2*i][n], t[kc+2*i+1][n]);
    *(uint4*)(dst + (size_t)(x0+n)*HID + y0 + kc) = *(uint4*)h;
}

__global__ void k_wd(const float* __restrict__ wd){
    __shared__ float t[64][33];
    int e = blockIdx.z;   // 0..7
    const size_t HI = (size_t)HID*INTERN;
    const float* src = wd  + (size_t)e*HI;
    __half* dst      = g_wdT + (size_t)e*HI;
    int tl = blockIdx.y*88 + blockIdx.x;          // 0..1407 = 32 x 44
    int x0 = (tl & 31)*32, y0 = (tl >> 5)*64;
    int tx = threadIdx.x, ty = threadIdx.y;
    int tid = ty*32 + tx;
    #pragma unroll
    for (int j=0;j<8;j++)
        t[ty+8*j][tx] = src[(size_t)(y0+ty+8*j)*HID + x0+tx];
    __syncthreads();
    int n = tid>>3, kc = (tid&7)*8;
    __half2 h[4];
    #pragma unroll
    for (int i=0;i<4;i++)
        h[i] = __floats2half2_rn(t[kc+2*i][n], t[kc+2*i+1][n]);
    *(uint4*)(dst + (size_t)(x0+n)*INTERN + y0 + kc) = *(uint4*)h;
}

// ---------------- router: fused x->fp16 + smem rw (conflict-free LDS.128) -----
#define RWP 12
__global__ void __launch_bounds__(256) k_router(const float* __restrict__ x,
                                                const float* __restrict__ rw){
    __shared__ float srw[HID*RWP];    // 48KB
    int tid = threadIdx.x;
    for (int idx = tid; idx < HID*NEXP; idx += 256)
        srw[(idx>>3)*RWP + (idx&7)] = rw[idx];
    __syncthreads();
    int warp = tid>>5, lane = tid&31;
    int tok = blockIdx.x*8 + warp;
    const float* xr = x + (size_t)tok*HID;
    __half* xh = g_xh + (size_t)tok*HID;
    float a0=0,a1=0,a2=0,a3=0,a4=0,a5=0,a6=0,a7=0;
    #pragma unroll 4
    for (int j=lane; j<HID; j+=32){
        float v = xr[j];
        xh[j] = __float2half_rn(v);          // fused x -> fp16 (reuses the LDG)
        const float4* r4 = (const float4*)&srw[j*RWP];
        float4 r0 = r4[0], r1 = r4[1];
        a0 += v*r0.x; a1 += v*r0.y; a2 += v*r0.z; a3 += v*r0.w;
        a4 += v*r1.x; a5 += v*r1.y; a6 += v*r1.z; a7 += v*r1.w;
    }
    float acc[NEXP] = {a0,a1,a2,a3,a4,a5,a6,a7};
    #pragma unroll
    for (int o=16;o>0;o>>=1)
        #pragma unroll
        for (int e=0;e<NEXP;e++) acc[e] += __shfl_down_sync(0xffffffffu, acc[e], o);
    if (lane==0){
        int i0=0; float l0=acc[0];
        #pragma unroll
        for (int e=1;e<NEXP;e++) if (acc[e]>l0){ l0=acc[e]; i0=e; }
        int i1=-1; float l1=-1e30f;
        #pragma unroll
        for (int e=0;e<NEXP;e++) if (e!=i0 && acc[e]>l1){ l1=acc[e]; i1=e; }
        float w0 = 1.f/(1.f + expf(l1 - l0));
        g_top_idx[tok*2+0]=i0; g_top_idx[tok*2+1]=i1;
        g_top_w[tok*2+0]=w0;   g_top_w[tok*2+1]=1.f-w0;
        atomicAdd(&g_cnt[i0],1); atomicAdd(&g_cnt[i1],1);
    }
}

// ---------------- scatter ------------------------------------------------------
__global__ void k_scatter(){
    int t = blockIdx.x*blockDim.x + threadIdx.x;
    if (t>=T_TOK) return;
    int base[NEXP]; int b=0;
    #pragma unroll
    for (int e=0;e<NEXP;e++){ base[e]=b; b += ((g_cnt[e]+BM-1)>>7)<<7; }
    #pragma unroll
    for (int k=0;k<2;k++){
        int e = g_top_idx[t*2+k];
        int pos = atomicAdd(&g_fill[e],1);
        int slot = base[e]+pos;
        g_slot_token[slot]=t;
        g_slot_w[slot]=g_top_w[t*2+k];
    }
}

// ============ GEMM1: 256 thr, warp 32x(32g+32u), 5-stage, sync per 2 kt =======
#define G1_ASTG (BM*PITCH)                 // 5120 halves
#define G1_BSTG (128*PITCH)                // 5120 halves
#define G1_SMEM ((G1_ASTG+G1_BSTG)*NSTG*2) // 102400 bytes

__global__ void __launch_bounds__(256,2) k_gemm1(){
    extern __shared__ __half smh[];
    TileInfo ti = resolve_tile(blockIdx.x);
    if (ti.e < 0) return;
    int slot0 = ti.slot0;
    int n0 = blockIdx.y*64;
    int tid=threadIdx.x, lane=tid&31, warp=tid>>5;
    int wm = warp>>1, wn = warp&1;
    uint32_t sA = s2u(smh);
    uint32_t sB = sA + NSTG*G1_ASTG*2;

    int lAr = lane & 15,              lAk = 8*(lane>>4);
    int lBr = (lane&7) + 8*(lane>>4), lBk = 8*((lane>>3)&1);

    int arow = tid>>1, ak = (tid&1)*16;
    int vrow = (slot0 + arow - ti.ebase) < ti.ecnt;
    int tok = vrow ? g_slot_token[slot0+arow] : 0;
    const __half* asrc = g_xh + (size_t)tok*HID + ak;
    int asz = vrow ? 16 : 0;
    int brow = tid>>1, bk = (tid&1)*16;
    const __half* bsrc = ((brow<64)? g_wgT + (size_t)ti.e*INTERN*HID + (size_t)(n0+brow)*HID
                                   : g_wuT + (size_t)ti.e*INTERN*HID + (size_t)(n0+brow-64)*HID) + bk;

    float cg[2][4][4], cu[2][4][4];
    #pragma unroll
    for (int i=0;i<2;i++)
        #pragma unroll
        for (int j=0;j<4;j++)
            #pragma unroll
            for (int r=0;r<4;r++){ cg[i][j][r]=0.f; cu[i][j][r]=0.f; }

    auto stage = [&](int s, int k0){
        uint32_t ad = sA + (uint32_t)(s*G1_ASTG + arow*PITCH + ak)*2;
        cp16(ad,      asrc + k0,     asz);
        cp16(ad + 16, asrc + k0 + 8, asz);
        uint32_t bd = sB + (uint32_t)(s*G1_BSTG + brow*PITCH + bk)*2;
        cp16(bd,      bsrc + k0,     16);
        cp16(bd + 16, bsrc + k0 + 8, 16);
        CP_COMMIT;
    };

    stage(0, 0); stage(1, BK); stage(2, 2*BK);
    const int NT = HID/BK;   // 32, even
    for (int j=0; j<NT; j+=2){
        CP_WAIT1;
        __syncthreads();
        int k3 = j+3, k4 = j+4;
        if (k3 < NT) stage(k3%NSTG, k3*BK); else CP_COMMIT;
        if (k4 < NT) stage(k4%NSTG, k4*BK); else CP_COMMIT;
        #pragma unroll
        for (int h=0; h<2; h++){
            int s = (j+h)%NSTG;
            uint32_t aoff = sA + (uint32_t)(s*G1_ASTG)*2;
            uint32_t boff = sB + (uint32_t)(s*G1_BSTG)*2;
            #pragma unroll
            for (int ks=0; ks<2; ks++){
                int kb = ks*16;
                uint32_t a0[4], a1[4];
                LDSM4(a0, aoff + (uint32_t)((wm*32     + lAr)*PITCH + kb + lAk)*2);
                LDSM4(a1, aoff + (uint32_t)((wm*32 +16 + lAr)*PITCH + kb + lAk)*2);
                #pragma unroll
                for (int nq=0;nq<2;nq++){
                    int c0 = wn*32 + nq*16;
                    uint32_t bg[4], bu[4];
                    LDSM4(bg, boff + (uint32_t)((c0    + lBr)*PITCH + kb + lBk)*2);
                    LDSM4(bu, boff + (uint32_t)((c0+64 + lBr)*PITCH + kb + lBk)*2);
                    MMA_F16(cg[0][nq*2+0], a0, bg+0);
                    MMA_F16(cg[0][nq*2+1], a0, bg+2);
                    MMA_F16(cg[1][nq*2+0], a1, bg+0);
                    MMA_F16(cg[1][nq*2+1], a1, bg+2);
                    MMA_F16(cu[0][nq*2+0], a0, bu+0);
                    MMA_F16(cu[0][nq*2+1], a0, bu+2);
                    MMA_F16(cu[1][nq*2+0], a1, bu+0);
                    MMA_F16(cu[1][nq*2+1], a1, bu+2);
                }
            }
        }
    }
    int g8 = lane>>2, tg = lane&3;
    #pragma unroll
    for (int mi=0;mi<2;mi++)
        #pragma unroll
        for (int ni=0;ni<4;ni++)
            #pragma unroll
            for (int rr=0;rr<2;rr++){
                int row = wm*32 + mi*16 + g8 + rr*8;
                int col = wn*32 + ni*8 + 2*tg;
                float g0 = cg[mi][ni][rr*2+0], u0 = cu[mi][ni][rr*2+0];
                float g1 = cg[mi][ni][rr*2+1], u1 = cu[mi][ni][rr*2+1];
                float v0 = u0 * (g0 / (1.f + expf(-g0)));
                float v1 = u1 * (g1 / (1.f + expf(-g1)));
                *(__half2*)(g_interh + (size_t)(slot0+row)*INTERN + n0 + col)
                    = __floats2half2_rn(v0, v1);
            }
}

// ============ GEMM2: 256 thr, warp 32x64, 5-stage/2kt, fused combine ==========
#define G2_ASTG (BM*PITCH)                 // 5120 halves
#define G2_BSTG (128*PITCH)                // 5120 halves
#define G2_SMEM ((G2_ASTG+G2_BSTG)*NSTG*2) // 102400 bytes

__global__ void __launch_bounds__(256,2) k_gemm2(float* __restrict__ out){
    extern __shared__ __half smh[];
    TileInfo ti = resolve_tile(blockIdx.x);
    if (ti.e < 0) return;
    int slot0 = ti.slot0;
    int n0 = blockIdx.y*128;
    int tid=threadIdx.x, lane=tid&31, warp=tid>>5;
    int wm = warp>>1, wn = warp&1;
    uint32_t sA = s2u(smh);
    uint32_t sB = sA + NSTG*G2_ASTG*2;

    int lAr = lane & 15,              lAk = 8*(lane>>4);
    int lBr = (lane&7) + 8*(lane>>4), lBk = 8*((lane>>3)&1);

    int arow = tid>>1, ak = (tid&1)*16;
    const __half* asrc = g_interh + (size_t)(slot0+arow)*INTERN + ak;
    int brow = tid>>1, bk = (tid&1)*16;
    const __half* bsrc = g_wdT + (size_t)ti.e*HID*INTERN + (size_t)(n0+brow)*INTERN + bk;

    float cc[2][8][4];
    #pragma unroll
    for (int i=0;i<2;i++)
        #pragma unroll
        for (int j=0;j<8;j++)
            #pragma unroll
            for (int r=0;r<4;r++) cc[i][j][r]=0.f;

    auto stage = [&](int s, int k0){
        uint32_t ad = sA + (uint32_t)(s*G2_ASTG + arow*PITCH + ak)*2;
        cp16(ad,      asrc + k0,     16);
        cp16(ad + 16, asrc + k0 + 8, 16);
        uint32_t bd = sB + (uint32_t)(s*G2_BSTG + brow*PITCH + bk)*2;
        cp16(bd,      bsrc + k0,     16);
        cp16(bd + 16, bsrc + k0 + 8, 16);
        CP_COMMIT;
    };

    stage(0, 0); stage(1, BK); stage(2, 2*BK);
    const int NT = INTERN/BK;   // 88, even
    for (int j=0; j<NT; j+=2){
        CP_WAIT1;
        __syncthreads();
        int k3 = j+3, k4 = j+4;
        if (k3 < NT) stage(k3%NSTG, k3*BK); else CP_COMMIT;
        if (k4 < NT) stage(k4%NSTG, k4*BK); else CP_COMMIT;
        #pragma unroll
        for (int h=0; h<2; h++){
            int s = (j+h)%NSTG;
            uint32_t aoff = sA + (uint32_t)(s*G2_ASTG)*2;
            uint32_t boff = sB + (uint32_t)(s*G2_BSTG)*2;
            #pragma unroll
            for (int ks=0; ks<2; ks++){
                int kb = ks*16;
                uint32_t a0[4], a1[4];
                LDSM4(a0, aoff + (uint32_t)((wm*32     + lAr)*PITCH + kb + lAk)*2);
                LDSM4(a1, aoff + (uint32_t)((wm*32 +16 + lAr)*PITCH + kb + lAk)*2);
                #pragma unroll
                for (int nq=0;nq<4;nq++){
                    int c0 = wn*64 + nq*16;
                    uint32_t bf[4];
                    LDSM4(bf, boff + (uint32_t)((c0 + lBr)*PITCH + kb + lBk)*2);
                    MMA_F16(cc[0][nq*2+0], a0, bf+0);
                    MMA_F16(cc[0][nq*2+1], a0, bf+2);
                    MMA_F16(cc[1][nq*2+0], a1, bf+0);
                    MMA_F16(cc[1][nq*2+1], a1, bf+2);
                }
            }
        }
    }
    // fused combine: out[token] += w_slot * val (2 commutative fp32 adds/elt)
    int g8 = lane>>2, tg = lane&3;
    #pragma unroll
    for (int mi=0;mi<2;mi++){
        #pragma unroll
        for (int rr=0;rr<2;rr++){
            int row = wm*32 + mi*16 + g8 + rr*8;
            if ((slot0 + row - ti.ebase) >= ti.ecnt) continue;
            int tokn = g_slot_token[slot0+row];
            float w  = g_slot_w[slot0+row];
            float* orow = out + (size_t)tokn*HID + n0;
            #pragma unroll
            for (int nj=0;nj<8;nj++){
                int col = wn*64 + (nj>>1)*16 + (nj&1)*8 + 2*tg;
                atomicAdd(orow + col,     w*cc[mi][nj][rr*2+0]);
                atomicAdd(orow + col + 1, w*cc[mi][nj][rr*2+1]);
            }
        }
    }
}

// ---------------- launch -----------------------------------------------------
extern "C" void kernel_launch(void* const* d_in, const int* in_sizes, int n_in,
                              void* d_out, int out_size){
    const float* x  = (const float*)d_in[0];
    const float* rw = (const float*)d_in[1];
    const float* wg = (const float*)d_in[2];
    const float* wu = (const float*)d_in[3];
    const float* wd = (const float*)d_in[4];
    float* out = (float*)d_out;

    static cudaStream_t s2 = nullptr, s3 = nullptr;
    static cudaEvent_t evR = nullptr, evW = nullptr, evD = nullptr;
    if (!s2){
        cudaStreamCreateWithFlags(&s2, cudaStreamNonBlocking);
        cudaStreamCreateWithFlags(&s3, cudaStreamNonBlocking);
        cudaEventCreateWithFlags(&evR, cudaEventDisableTiming);
        cudaEventCreateWithFlags(&evW, cudaEventDisableTiming);
        cudaEventCreateWithFlags(&evD, cudaEventDisableTiming);
        cudaFuncSetAttribute(k_gemm1, cudaFuncAttributeMaxDynamicSharedMemorySize, G1_SMEM);
        cudaFuncSetAttribute(k_gemm2, cudaFuncAttributeMaxDynamicSharedMemorySize, G2_SMEM);
    }

    void *cntp, *fillp;
    cudaGetSymbolAddress(&cntp,  g_cnt);
    cudaGetSymbolAddress(&fillp, g_fill);
    cudaMemsetAsync(cntp,  0, NEXP*sizeof(int), 0);
    cudaMemsetAsync(fillp, 0, NEXP*sizeof(int), 0);
    cudaMemsetAsync(out, 0, (size_t)out_size*sizeof(float), 0);

    // fork: weight conversions on side streams
    cudaEventRecord(evR, 0);
    cudaStreamWaitEvent(s2, evR, 0);
    cudaStreamWaitEvent(s3, evR, 0);
    k_wgu<<<dim3(88, 16, 16), dim3(32,8), 0, s2>>>(wg, wu);
    cudaEventRecord(evW, s2);
    k_wd<<<dim3(88, 16, 8), dim3(32,8), 0, s3>>>(wd);
    cudaEventRecord(evD, s3);

    // main stream: routing chain (concurrent with weight conversion)
    k_router<<<T_TOK/8, 256>>>(x, rw);
    k_scatter<<<(T_TOK+255)/256, 256>>>();

    // join: gemm1 needs wg/wu; gemm2 additionally needs wd
    cudaStreamWaitEvent(0, evW, 0);
    k_gemm1<<<dim3(MAXTILES, INTERN/64), 256, G1_SMEM>>>();
    cudaStreamWaitEvent(0, evD, 0);
    k_gemm2<<<dim3(MAXTILES, HID/128), 256, G2_SMEM>>>(out);
}

// round 16
// speedup vs baseline: 1.0522x; 1.0048x over previous
#include <cuda_runtime.h>
#include <cuda_fp16.h>
#include <cstdint>

#define T_TOK 8192
#define HID   1024
#define NEXP  8
#define INTERN 2816
#define BM 128
#define BK 32                  // k halves per stage
#define NSTG 5
#define MAXTILES 136
#define SLOT_CAP (MAXTILES*BM)
#define PITCH 40               // smem row pitch in halves (80B)

// ---------------- device scratch -------------------------------------------
__device__ int    g_top_idx[T_TOK*2];
__device__ float  g_top_w[T_TOK*2];
__device__ int    g_cnt[NEXP];
__device__ int    g_fill[NEXP];
__device__ int    g_slot_token[SLOT_CAP];
__device__ float  g_slot_w[SLOT_CAP];
__device__ __half g_xh[(size_t)T_TOK*HID];
__device__ __half g_wgT[(size_t)NEXP*INTERN*HID];   // [e][n=I][k=H]
__device__ __half g_wuT[(size_t)NEXP*INTERN*HID];
__device__ __half g_wdT[(size_t)NEXP*HID*INTERN];   // [e][n=H][k=I]
__device__ __half g_interh[(size_t)SLOT_CAP*INTERN];

// ---------------- helpers ----------------------------------------------------
__device__ __forceinline__ void cp16(uint32_t dst, const void* src, int sz){
    asm volatile("cp.async.cg.shared.global [%0], [%1], 16, %2;\n" :: "r"(dst), "l"(src), "r"(sz));
}
#define CP_COMMIT asm volatile("cp.async.commit_group;\n" ::: "memory")
#define CP_WAIT1  asm volatile("cp.async.wait_group 1;\n" ::: "memory")

#define MMA_F16(c,a,b) \
  asm volatile("mma.sync.aligned.m16n8k16.row.col.f32.f16.f16.f32 " \
               "{%0,%1,%2,%3},{%4,%5,%6,%7},{%8,%9},{%0,%1,%2,%3};" \
               : "+f"((c)[0]),"+f"((c)[1]),"+f"((c)[2]),"+f"((c)[3]) \
               : "r"((a)[0]),"r"((a)[1]),"r"((a)[2]),"r"((a)[3]), \
                 "r"((b)[0]),"r"((b)[1]))

#define LDSM4(r, addr) \
  asm volatile("ldmatrix.sync.aligned.m8n8.x4.shared.b16 {%0,%1,%2,%3}, [%4];" \
               : "=r"((r)[0]),"=r"((r)[1]),"=r"((r)[2]),"=r"((r)[3]) : "r"(addr))

__device__ __forceinline__ uint32_t s2u(const void* p){
    uint32_t a;
    asm("{ .reg .u64 t; cvta.to.shared.u64 t, %1; cvt.u32.u64 %0, t; }" : "=r"(a) : "l"(p));
    return a;
}

struct TileInfo { int e, slot0, ebase, ecnt; };
__device__ __forceinline__ TileInfo resolve_tile(int bx){
    TileInfo ti; ti.e = -1; ti.slot0 = 0; ti.ebase = 0; ti.ecnt = 0;
    int tacc = 0, base = 0;
    #pragma unroll
    for (int i=0;i<NEXP;i++){
        int c = g_cnt[i];
        int nt = (c + BM - 1) >> 7;
        if (ti.e < 0 && bx < tacc + nt){
            ti.e = i; ti.slot0 = base + (bx - tacc)*BM; ti.ebase = base; ti.ecnt = c;
        }
        tacc += nt; base += nt*BM;
    }
    return ti;
}

// ---------------- weight transpose kernels (fast 64Kx32N tiles) ---------------
__global__ void k_wgu(const float* __restrict__ wg, const float* __restrict__ wu){
    __shared__ float t[64][33];
    int z = blockIdx.z;   // 0..15
    const size_t HI = (size_t)HID*INTERN;
    const float* src; __half* dst;
    if (z < 8){ src = wg + (size_t)z*HI;     dst = g_wgT + (size_t)z*HI; }
    else      { src = wu + (size_t)(z-8)*HI; dst = g_wuT + (size_t)(z-8)*HI; }
    int x0 = blockIdx.x*32, y0 = blockIdx.y*64;
    int tx = threadIdx.x, ty = threadIdx.y;       // 32 x 8
    int tid = ty*32 + tx;
    #pragma unroll
    for (int j=0;j<8;j++)
        t[ty+8*j][tx] = src[(size_t)(y0+ty+8*j)*INTERN + x0+tx];
    __syncthreads();
    int n = tid>>3, kc = (tid&7)*8;
    __half2 h[4];
    #pragma unroll
    for (int i=0;i<4;i++)
        h[i] = __floats2half2_rn(t[kc+2*i][n], t[kc+2*i+1][n]);
    *(uint4*)(dst + (size_t)(x0+n)*HID + y0 + kc) = *(uint4*)h;
}

__global__ void k_wd(const float* __restrict__ wd){
    __shared__ float t[64][33];
    int e = blockIdx.z;   // 0..7
    const size_t HI = (size_t)HID*INTERN;
    const float* src = wd  + (size_t)e*HI;
    __half* dst      = g_wdT + (size_t)e*HI;
    int tl = blockIdx.y*88 + blockIdx.x;          // 0..1407 = 32 x 44
    int x0 = (tl & 31)*32, y0 = (tl >> 5)*64;
    int tx = threadIdx.x, ty = threadIdx.y;
    int tid = ty*32 + tx;
    #pragma unroll
    for (int j=0;j<8;j++)
        t[ty+8*j][tx] = src[(size_t)(y0+ty+8*j)*HID + x0+tx];
    __syncthreads();
    int n = tid>>3, kc = (tid&7)*8;
    __half2 h[4];
    #pragma unroll
    for (int i=0;i<4;i++)
        h[i] = __floats2half2_rn(t[kc+2*i][n], t[kc+2*i+1][n]);
    *(uint4*)(dst + (size_t)(x0+n)*INTERN + y0 + kc) = *(uint4*)h;
}

// ---------------- router: fused x->fp16 + smem rw (conflict-free LDS.128) -----
#define RWP 12
__global__ void __launch_bounds__(256) k_router(const float* __restrict__ x,
                                                const float* __restrict__ rw){
    __shared__ float srw[HID*RWP];    // 48KB
    int tid = threadIdx.x;
    for (int idx = tid; idx < HID*NEXP; idx += 256)
        srw[(idx>>3)*RWP + (idx&7)] = rw[idx];
    __syncthreads();
    int warp = tid>>5, lane = tid&31;
    int tok = blockIdx.x*8 + warp;
    const float* xr = x + (size_t)tok*HID;
    __half* xh = g_xh + (size_t)tok*HID;
    float a0=0,a1=0,a2=0,a3=0,a4=0,a5=0,a6=0,a7=0;
    #pragma unroll 4
    for (int j=lane; j<HID; j+=32){
        float v = xr[j];
        xh[j] = __float2half_rn(v);          // fused x -> fp16 (reuses the LDG)
        const float4* r4 = (const float4*)&srw[j*RWP];
        float4 r0 = r4[0], r1 = r4[1];
        a0 += v*r0.x; a1 += v*r0.y; a2 += v*r0.z; a3 += v*r0.w;
        a4 += v*r1.x; a5 += v*r1.y; a6 += v*r1.z; a7 += v*r1.w;
    }
    float acc[NEXP] = {a0,a1,a2,a3,a4,a5,a6,a7};
    #pragma unroll
    for (int o=16;o>0;o>>=1)
        #pragma unroll
        for (int e=0;e<NEXP;e++) acc[e] += __shfl_down_sync(0xffffffffu, acc[e], o);
    if (lane==0){
        int i0=0; float l0=acc[0];
        #pragma unroll
        for (int e=1;e<NEXP;e++) if (acc[e]>l0){ l0=acc[e]; i0=e; }
        int i1=-1; float l1=-1e30f;
        #pragma unroll
        for (int e=0;e<NEXP;e++) if (e!=i0 && acc[e]>l1){ l1=acc[e]; i1=e; }
        float w0 = 1.f/(1.f + expf(l1 - l0));
        g_top_idx[tok*2+0]=i0; g_top_idx[tok*2+1]=i1;
        g_top_w[tok*2+0]=w0;   g_top_w[tok*2+1]=1.f-w0;
        atomicAdd(&g_cnt[i0],1); atomicAdd(&g_cnt[i1],1);
    }
}

// ---------------- scatter ------------------------------------------------------
__global__ void k_scatter(){
    int t = blockIdx.x*blockDim.x + threadIdx.x;
    if (t>=T_TOK) return;
    int base[NEXP]; int b=0;
    #pragma unroll
    for (int e=0;e<NEXP;e++){ base[e]=b; b += ((g_cnt[e]+BM-1)>>7)<<7; }
    #pragma unroll
    for (int k=0;k<2;k++){
        int e = g_top_idx[t*2+k];
        int pos = atomicAdd(&g_fill[e],1);
        int slot = base[e]+pos;
        g_slot_token[slot]=t;
        g_slot_w[slot]=g_top_w[t*2+k];
    }
}

// ============ GEMM1: 256 thr, warp 32x(32g+32u), 5-stage, sync per 2 kt =======
#define G1_ASTG (BM*PITCH)                 // 5120 halves
#define G1_BSTG (128*PITCH)                // 5120 halves
#define G1_SMEM ((G1_ASTG+G1_BSTG)*NSTG*2) // 102400 bytes

__global__ void __launch_bounds__(256,2) k_gemm1(){
    extern __shared__ __half smh[];
    TileInfo ti = resolve_tile(blockIdx.x);
    if (ti.e < 0) return;
    int slot0 = ti.slot0;
    int n0 = blockIdx.y*64;
    int tid=threadIdx.x, lane=tid&31, warp=tid>>5;
    int wm = warp>>1, wn = warp&1;
    uint32_t sA = s2u(smh);
    uint32_t sB = sA + NSTG*G1_ASTG*2;

    int lAr = lane & 15,              lAk = 8*(lane>>4);
    int lBr = (lane&7) + 8*(lane>>4), lBk = 8*((lane>>3)&1);

    int arow = tid>>1, ak = (tid&1)*16;
    int vrow = (slot0 + arow - ti.ebase) < ti.ecnt;
    int tok = vrow ? g_slot_token[slot0+arow] : 0;
    const __half* asrc = g_xh + (size_t)tok*HID + ak;
    int asz = vrow ? 16 : 0;
    int brow = tid>>1, bk = (tid&1)*16;
    const __half* bsrc = ((brow<64)? g_wgT + (size_t)ti.e*INTERN*HID + (size_t)(n0+brow)*HID
                                   : g_wuT + (size_t)ti.e*INTERN*HID + (size_t)(n0+brow-64)*HID) + bk;

    float cg[2][4][4], cu[2][4][4];
    #pragma unroll
    for (int i=0;i<2;i++)
        #pragma unroll
        for (int j=0;j<4;j++)
            #pragma unroll
            for (int r=0;r<4;r++){ cg[i][j][r]=0.f; cu[i][j][r]=0.f; }

    auto stage = [&](int s, int k0){
        uint32_t ad = sA + (uint32_t)(s*G1_ASTG + arow*PITCH + ak)*2;
        cp16(ad,      asrc + k0,     asz);
        cp16(ad + 16, asrc + k0 + 8, asz);
        uint32_t bd = sB + (uint32_t)(s*G1_BSTG + brow*PITCH + bk)*2;
        cp16(bd,      bsrc + k0,     16);
        cp16(bd + 16, bsrc + k0 + 8, 16);
        CP_COMMIT;
    };

    stage(0, 0); stage(1, BK); stage(2, 2*BK);
    const int NT = HID/BK;   // 32, even
    for (int j=0; j<NT; j+=2){
        CP_WAIT1;
        __syncthreads();
        int k3 = j+3, k4 = j+4;
        if (k3 < NT) stage(k3%NSTG, k3*BK); else CP_COMMIT;
        if (k4 < NT) stage(k4%NSTG, k4*BK); else CP_COMMIT;
        #pragma unroll
        for (int h=0; h<2; h++){
            int s = (j+h)%NSTG;
            uint32_t aoff = sA + (uint32_t)(s*G1_ASTG)*2;
            uint32_t boff = sB + (uint32_t)(s*G1_BSTG)*2;
            #pragma unroll
            for (int ks=0; ks<2; ks++){
                int kb = ks*16;
                uint32_t a0[4], a1[4];
                LDSM4(a0, aoff + (uint32_t)((wm*32     + lAr)*PITCH + kb + lAk)*2);
                LDSM4(a1, aoff + (uint32_t)((wm*32 +16 + lAr)*PITCH + kb + lAk)*2);
                #pragma unroll
                for (int nq=0;nq<2;nq++){
                    int c0 = wn*32 + nq*16;
                    uint32_t bg[4], bu[4];
                    LDSM4(bg, boff + (uint32_t)((c0    + lBr)*PITCH + kb + lBk)*2);
                    LDSM4(bu, boff + (uint32_t)((c0+64 + lBr)*PITCH + kb + lBk)*2);
                    MMA_F16(cg[0][nq*2+0], a0, bg+0);
                    MMA_F16(cg[0][nq*2+1], a0, bg+2);
                    MMA_F16(cg[1][nq*2+0], a1, bg+0);
                    MMA_F16(cg[1][nq*2+1], a1, bg+2);
                    MMA_F16(cu[0][nq*2+0], a0, bu+0);
                    MMA_F16(cu[0][nq*2+1], a0, bu+2);
                    MMA_F16(cu[1][nq*2+0], a1, bu+0);
                    MMA_F16(cu[1][nq*2+1], a1, bu+2);
                }
            }
        }
    }
    int g8 = lane>>2, tg = lane&3;
    #pragma unroll
    for (int mi=0;mi<2;mi++)
        #pragma unroll
        for (int ni=0;ni<4;ni++)
            #pragma unroll
            for (int rr=0;rr<2;rr++){
                int row = wm*32 + mi*16 + g8 + rr*8;
                int col = wn*32 + ni*8 + 2*tg;
                float g0 = cg[mi][ni][rr*2+0], u0 = cu[mi][ni][rr*2+0];
                float g1 = cg[mi][ni][rr*2+1], u1 = cu[mi][ni][rr*2+1];
                float v0 = u0 * (g0 / (1.f + expf(-g0)));
                float v1 = u1 * (g1 / (1.f + expf(-g1)));
                *(__half2*)(g_interh + (size_t)(slot0+row)*INTERN + n0 + col)
                    = __floats2half2_rn(v0, v1);
            }
}

// ============ GEMM2: grid (n-blocks fast, tiles slow) for L2 A-panel reuse ====
#define G2_ASTG (BM*PITCH)                 // 5120 halves
#define G2_BSTG (128*PITCH)                // 5120 halves
#define G2_SMEM ((G2_ASTG+G2_BSTG)*NSTG*2) // 102400 bytes

__global__ void __launch_bounds__(256,2) k_gemm2(float* __restrict__ out){
    extern __shared__ __half smh[];
    TileInfo ti = resolve_tile(blockIdx.y);          // tile on y (slow axis)
    if (ti.e < 0) return;
    int slot0 = ti.slot0;
    int n0 = blockIdx.x*128;                         // n-block on x (fast axis)
    int tid=threadIdx.x, lane=tid&31, warp=tid>>5;
    int wm = warp>>1, wn = warp&1;
    uint32_t sA = s2u(smh);
    uint32_t sB = sA + NSTG*G2_ASTG*2;

    int lAr = lane & 15,              lAk = 8*(lane>>4);
    int lBr = (lane&7) + 8*(lane>>4), lBk = 8*((lane>>3)&1);

    int arow = tid>>1, ak = (tid&1)*16;
    const __half* asrc = g_interh + (size_t)(slot0+arow)*INTERN + ak;
    int brow = tid>>1, bk = (tid&1)*16;
    const __half* bsrc = g_wdT + (size_t)ti.e*HID*INTERN + (size_t)(n0+brow)*INTERN + bk;

    float cc[2][8][4];
    #pragma unroll
    for (int i=0;i<2;i++)
        #pragma unroll
        for (int j=0;j<8;j++)
            #pragma unroll
            for (int r=0;r<4;r++) cc[i][j][r]=0.f;

    auto stage = [&](int s, int k0){
        uint32_t ad = sA + (uint32_t)(s*G2_ASTG + arow*PITCH + ak)*2;
        cp16(ad,      asrc + k0,     16);
        cp16(ad + 16, asrc + k0 + 8, 16);
        uint32_t bd = sB + (uint32_t)(s*G2_BSTG + brow*PITCH + bk)*2;
        cp16(bd,      bsrc + k0,     16);
        cp16(bd + 16, bsrc + k0 + 8, 16);
        CP_COMMIT;
    };

    stage(0, 0); stage(1, BK); stage(2, 2*BK);
    const int NT = INTERN/BK;   // 88, even
    for (int j=0; j<NT; j+=2){
        CP_WAIT1;
        __syncthreads();
        int k3 = j+3, k4 = j+4;
        if (k3 < NT) stage(k3%NSTG, k3*BK); else CP_COMMIT;
        if (k4 < NT) stage(k4%NSTG, k4*BK); else CP_COMMIT;
        #pragma unroll
        for (int h=0; h<2; h++){
            int s = (j+h)%NSTG;
            uint32_t aoff = sA + (uint32_t)(s*G2_ASTG)*2;
            uint32_t boff = sB + (uint32_t)(s*G2_BSTG)*2;
            #pragma unroll
            for (int ks=0; ks<2; ks++){
                int kb = ks*16;
                uint32_t a0[4], a1[4];
                LDSM4(a0, aoff + (uint32_t)((wm*32     + lAr)*PITCH + kb + lAk)*2);
                LDSM4(a1, aoff + (uint32_t)((wm*32 +16 + lAr)*PITCH + kb + lAk)*2);
                #pragma unroll
                for (int nq=0;nq<4;nq++){
                    int c0 = wn*64 + nq*16;
                    uint32_t bf[4];
                    LDSM4(bf, boff + (uint32_t)((c0 + lBr)*PITCH + kb + lBk)*2);
                    MMA_F16(cc[0][nq*2+0], a0, bf+0);
                    MMA_F16(cc[0][nq*2+1], a0, bf+2);
                    MMA_F16(cc[1][nq*2+0], a1, bf+0);
                    MMA_F16(cc[1][nq*2+1], a1, bf+2);
                }
            }
        }
    }
    // fused combine: out[token] += w_slot * val (2 commutative fp32 adds/elt)
    int g8 = lane>>2, tg = lane&3;
    #pragma unroll
    for (int mi=0;mi<2;mi++){
        #pragma unroll
        for (int rr=0;rr<2;rr++){
            int row = wm*32 + mi*16 + g8 + rr*8;
            if ((slot0 + row - ti.ebase) >= ti.ecnt) continue;
            int tokn = g_slot_token[slot0+row];
            float w  = g_slot_w[slot0+row];
            float* orow = out + (size_t)tokn*HID + n0;
            #pragma unroll
            for (int nj=0;nj<8;nj++){
                int col = wn*64 + (nj>>1)*16 + (nj&1)*8 + 2*tg;
                atomicAdd(orow + col,     w*cc[mi][nj][rr*2+0]);
                atomicAdd(orow + col + 1, w*cc[mi][nj][rr*2+1]);
            }
        }
    }
}

// ---------------- launch -----------------------------------------------------
extern "C" void kernel_launch(void* const* d_in, const int* in_sizes, int n_in,
                              void* d_out, int out_size){
    const float* x  = (const float*)d_in[0];
    const float* rw = (const float*)d_in[1];
    const float* wg = (const float*)d_in[2];
    const float* wu = (const float*)d_in[3];
    const float* wd = (const float*)d_in[4];
    float* out = (float*)d_out;

    static cudaStream_t s2 = nullptr, s3 = nullptr;
    static cudaEvent_t evR = nullptr, evW = nullptr, evD = nullptr;
    if (!s2){
        cudaStreamCreateWithFlags(&s2, cudaStreamNonBlocking);
        cudaStreamCreateWithFlags(&s3, cudaStreamNonBlocking);
        cudaEventCreateWithFlags(&evR, cudaEventDisableTiming);
        cudaEventCreateWithFlags(&evW, cudaEventDisableTiming);
        cudaEventCreateWithFlags(&evD, cudaEventDisableTiming);
        cudaFuncSetAttribute(k_gemm1, cudaFuncAttributeMaxDynamicSharedMemorySize, G1_SMEM);
        cudaFuncSetAttribute(k_gemm2, cudaFuncAttributeMaxDynamicSharedMemorySize, G2_SMEM);
    }

    void *cntp, *fillp;
    cudaGetSymbolAddress(&cntp,  g_cnt);
    cudaGetSymbolAddress(&fillp, g_fill);
    cudaMemsetAsync(cntp,  0, NEXP*sizeof(int), 0);
    cudaMemsetAsync(fillp, 0, NEXP*sizeof(int), 0);

    // fork: weight conversions on side streams; out-zeroing rides s3 (only
    // gemm2 consumes it, and gemm2 already joins on evD)
    cudaEventRecord(evR, 0);
    cudaStreamWaitEvent(s2, evR, 0);
    cudaStreamWaitEvent(s3, evR, 0);
    k_wgu<<<dim3(88, 16, 16), dim3(32,8), 0, s2>>>(wg, wu);
    cudaEventRecord(evW, s2);
    cudaMemsetAsync(out, 0, (size_t)out_size*sizeof(float), s3);
    k_wd<<<dim3(88, 16, 8), dim3(32,8), 0, s3>>>(wd);
    cudaEventRecord(evD, s3);

    // main stream: routing chain (concurrent with weight conversion)
    k_router<<<T_TOK/8, 256>>>(x, rw);
    k_scatter<<<(T_TOK+255)/256, 256>>>();

    // join: gemm1 needs wg/wu; gemm2 additionally needs wd + zeroed out
    cudaStreamWaitEvent(0, evW, 0);
    k_gemm1<<<dim3(MAXTILES, INTERN/64), 256, G1_SMEM>>>();
    cudaStreamWaitEvent(0, evD, 0);
    k_gemm2<<<dim3(HID/128, MAXTILES), 256, G2_SMEM>>>(out);
}

// round 17
// speedup vs baseline: 1.0567x; 1.0043x over previous
#include <cuda_runtime.h>
#include <cuda_fp16.h>
#include <cstdint>

#define T_TOK 8192
#define HID   1024
#define NEXP  8
#define INTERN 2816
#define BM 128
#define BK 32                  // k halves per stage
#define NSTG 5
#define MAXTILES 136
#define SLOT_CAP (MAXTILES*BM)
#define PITCH 40               // smem row pitch in halves (80B)

// ---------------- device scratch -------------------------------------------
__device__ int    g_top_idx[T_TOK*2];
__device__ float  g_top_w[T_TOK*2];
__device__ int    g_cnt[NEXP];
__device__ int    g_fill[NEXP];
__device__ int    g_slot_token[SLOT_CAP];
__device__ float  g_slot_w[SLOT_CAP];
__device__ __half g_xh[(size_t)T_TOK*HID];
__device__ __half g_wgT[(size_t)NEXP*INTERN*HID];   // [e][n=I][k=H]
__device__ __half g_wuT[(size_t)NEXP*INTERN*HID];
__device__ __half g_wdT[(size_t)NEXP*HID*INTERN];   // [e][n=H][k=I]
__device__ __half g_interh[(size_t)SLOT_CAP*INTERN];

// ---------------- helpers ----------------------------------------------------
__device__ __forceinline__ void cp16(uint32_t dst, const void* src, int sz){
    asm volatile("cp.async.cg.shared.global [%0], [%1], 16, %2;\n" :: "r"(dst), "l"(src), "r"(sz));
}
#define CP_COMMIT asm volatile("cp.async.commit_group;\n" ::: "memory")
#define CP_WAIT1  asm volatile("cp.async.wait_group 1;\n" ::: "memory")

#define MMA_F16(c,a,b) \
  asm volatile("mma.sync.aligned.m16n8k16.row.col.f32.f16.f16.f32 " \
               "{%0,%1,%2,%3},{%4,%5,%6,%7},{%8,%9},{%0,%1,%2,%3};" \
               : "+f"((c)[0]),"+f"((c)[1]),"+f"((c)[2]),"+f"((c)[3]) \
               : "r"((a)[0]),"r"((a)[1]),"r"((a)[2]),"r"((a)[3]), \
                 "r"((b)[0]),"r"((b)[1]))

#define LDSM4(r, addr) \
  asm volatile("ldmatrix.sync.aligned.m8n8.x4.shared.b16 {%0,%1,%2,%3}, [%4];" \
               : "=r"((r)[0]),"=r"((r)[1]),"=r"((r)[2]),"=r"((r)[3]) : "r"(addr))

// vectorized fire-and-forget reduction (sm_90+): out[0]+=v0, out[1]+=v1
#define REDV2(ptr, v0, v1) \
  asm volatile("red.global.add.v2.f32 [%0], {%1, %2};" \
               :: "l"(ptr), "f"(v0), "f"(v1) : "memory")

__device__ __forceinline__ uint32_t s2u(const void* p){
    uint32_t a;
    asm("{ .reg .u64 t; cvta.to.shared.u64 t, %1; cvt.u32.u64 %0, t; }" : "=r"(a) : "l"(p));
    return a;
}

struct TileInfo { int e, slot0, ebase, ecnt; };
__device__ __forceinline__ TileInfo resolve_tile(int bx){
    TileInfo ti; ti.e = -1; ti.slot0 = 0; ti.ebase = 0; ti.ecnt = 0;
    int tacc = 0, base = 0;
    #pragma unroll
    for (int i=0;i<NEXP;i++){
        int c = g_cnt[i];
        int nt = (c + BM - 1) >> 7;
        if (ti.e < 0 && bx < tacc + nt){
            ti.e = i; ti.slot0 = base + (bx - tacc)*BM; ti.ebase = base; ti.ecnt = c;
        }
        tacc += nt; base += nt*BM;
    }
    return ti;
}

// ---------------- weight transpose kernels (fast 64Kx32N tiles) ---------------
__global__ void k_wgu(const float* __restrict__ wg, const float* __restrict__ wu){
    __shared__ float t[64][33];
    int z = blockIdx.z;   // 0..15
    const size_t HI = (size_t)HID*INTERN;
    const float* src; __half* dst;
    if (z < 8){ src = wg + (size_t)z*HI;     dst = g_wgT + (size_t)z*HI; }
    else      { src = wu + (size_t)(z-8)*HI; dst = g_wuT + (size_t)(z-8)*HI; }
    int x0 = blockIdx.x*32, y0 = blockIdx.y*64;
    int tx = threadIdx.x, ty = threadIdx.y;       // 32 x 8
    int tid = ty*32 + tx;
    #pragma unroll
    for (int j=0;j<8;j++)
        t[ty+8*j][tx] = src[(size_t)(y0+ty+8*j)*INTERN + x0+tx];
    __syncthreads();
    int n = tid>>3, kc = (tid&7)*8;
    __half2 h[4];
    #pragma unroll
    for (int i=0;i<4;i++)
        h[i] = __floats2half2_rn(t[kc+2*i][n], t[kc+2*i+1][n]);
    *(uint4*)(dst + (size_t)(x0+n)*HID + y0 + kc) = *(uint4*)h;
}

__global__ void k_wd(const float* __restrict__ wd){
    __shared__ float t[64][33];
    int e = blockIdx.z;   // 0..7
    const size_t HI = (size_t)HID*INTERN;
    const float* src = wd  + (size_t)e*HI;
    __half* dst      = g_wdT + (size_t)e*HI;
    int tl = blockIdx.y*88 + blockIdx.x;          // 0..1407 = 32 x 44
    int x0 = (tl & 31)*32, y0 = (tl >> 5)*64;
    int tx = threadIdx.x, ty = threadIdx.y;
    int tid = ty*32 + tx;
    #pragma unroll
    for (int j=0;j<8;j++)
        t[ty+8*j][tx] = src[(size_t)(y0+ty+8*j)*HID + x0+tx];
    __syncthreads();
    int n = tid>>3, kc = (tid&7)*8;
    __half2 h[4];
    #pragma unroll
    for (int i=0;i<4;i++)
        h[i] = __floats2half2_rn(t[kc+2*i][n], t[kc+2*i+1][n]);
    *(uint4*)(dst + (size_t)(x0+n)*INTERN + y0 + kc) = *(uint4*)h;
}

// ---------------- router: fused x->fp16 + smem rw (conflict-free LDS.128) -----
#define RWP 12
__global__ void __launch_bounds__(256) k_router(const float* __restrict__ x,
                                                const float* __restrict__ rw){
    __shared__ float srw[HID*RWP];    // 48KB
    int tid = threadIdx.x;
    for (int idx = tid; idx < HID*NEXP; idx += 256)
        srw[(idx>>3)*RWP + (idx&7)] = rw[idx];
    __syncthreads();
    int warp = tid>>5, lane = tid&31;
    int tok = blockIdx.x*8 + warp;
    const float* xr = x + (size_t)tok*HID;
    __half* xh = g_xh + (size_t)tok*HID;
    float a0=0,a1=0,a2=0,a3=0,a4=0,a5=0,a6=0,a7=0;
    #pragma unroll 4
    for (int j=lane; j<HID; j+=32){
        float v = xr[j];
        xh[j] = __float2half_rn(v);          // fused x -> fp16 (reuses the LDG)
        const float4* r4 = (const float4*)&srw[j*RWP];
        float4 r0 = r4[0], r1 = r4[1];
        a0 += v*r0.x; a1 += v*r0.y; a2 += v*r0.z; a3 += v*r0.w;
        a4 += v*r1.x; a5 += v*r1.y; a6 += v*r1.z; a7 += v*r1.w;
    }
    float acc[NEXP] = {a0,a1,a2,a3,a4,a5,a6,a7};
    #pragma unroll
    for (int o=16;o>0;o>>=1)
        #pragma unroll
        for (int e=0;e<NEXP;e++) acc[e] += __shfl_down_sync(0xffffffffu, acc[e], o);
    if (lane==0){
        int i0=0; float l0=acc[0];
        #pragma unroll
        for (int e=1;e<NEXP;e++) if (acc[e]>l0){ l0=acc[e]; i0=e; }
        int i1=-1; float l1=-1e30f;
        #pragma unroll
        for (int e=0;e<NEXP;e++) if (e!=i0 && acc[e]>l1){ l1=acc[e]; i1=e; }
        float w0 = 1.f/(1.f + expf(l1 - l0));
        g_top_idx[tok*2+0]=i0; g_top_idx[tok*2+1]=i1;
        g_top_w[tok*2+0]=w0;   g_top_w[tok*2+1]=1.f-w0;
        atomicAdd(&g_cnt[i0],1); atomicAdd(&g_cnt[i1],1);
    }
}

// ---------------- scatter ------------------------------------------------------
__global__ void k_scatter(){
    int t = blockIdx.x*blockDim.x + threadIdx.x;
    if (t>=T_TOK) return;
    int base[NEXP]; int b=0;
    #pragma unroll
    for (int e=0;e<NEXP;e++){ base[e]=b; b += ((g_cnt[e]+BM-1)>>7)<<7; }
    #pragma unroll
    for (int k=0;k<2;k++){
        int e = g_top_idx[t*2+k];
        int pos = atomicAdd(&g_fill[e],1);
        int slot = base[e]+pos;
        g_slot_token[slot]=t;
        g_slot_w[slot]=g_top_w[t*2+k];
    }
}

// ============ GEMM1: 256 thr, warp 32x(32g+32u), 5-stage, sync per 2 kt =======
#define G1_ASTG (BM*PITCH)                 // 5120 halves
#define G1_BSTG (128*PITCH)                // 5120 halves
#define G1_SMEM ((G1_ASTG+G1_BSTG)*NSTG*2) // 102400 bytes

__global__ void __launch_bounds__(256,2) k_gemm1(){
    extern __shared__ __half smh[];
    TileInfo ti = resolve_tile(blockIdx.x);
    if (ti.e < 0) return;
    int slot0 = ti.slot0;
    int n0 = blockIdx.y*64;
    int tid=threadIdx.x, lane=tid&31, warp=tid>>5;
    int wm = warp>>1, wn = warp&1;
    uint32_t sA = s2u(smh);
    uint32_t sB = sA + NSTG*G1_ASTG*2;

    int lAr = lane & 15,              lAk = 8*(lane>>4);
    int lBr = (lane&7) + 8*(lane>>4), lBk = 8*((lane>>3)&1);

    int arow = tid>>1, ak = (tid&1)*16;
    int vrow = (slot0 + arow - ti.ebase) < ti.ecnt;
    int tok = vrow ? g_slot_token[slot0+arow] : 0;
    const __half* asrc = g_xh + (size_t)tok*HID + ak;
    int asz = vrow ? 16 : 0;
    int brow = tid>>1, bk = (tid&1)*16;
    const __half* bsrc = ((brow<64)? g_wgT + (size_t)ti.e*INTERN*HID + (size_t)(n0+brow)*HID
                                   : g_wuT + (size_t)ti.e*INTERN*HID + (size_t)(n0+brow-64)*HID) + bk;

    float cg[2][4][4], cu[2][4][4];
    #pragma unroll
    for (int i=0;i<2;i++)
        #pragma unroll
        for (int j=0;j<4;j++)
            #pragma unroll
            for (int r=0;r<4;r++){ cg[i][j][r]=0.f; cu[i][j][r]=0.f; }

    auto stage = [&](int s, int k0){
        uint32_t ad = sA + (uint32_t)(s*G1_ASTG + arow*PITCH + ak)*2;
        cp16(ad,      asrc + k0,     asz);
        cp16(ad + 16, asrc + k0 + 8, asz);
        uint32_t bd = sB + (uint32_t)(s*G1_BSTG + brow*PITCH + bk)*2;
        cp16(bd,      bsrc + k0,     16);
        cp16(bd + 16, bsrc + k0 + 8, 16);
        CP_COMMIT;
    };

    stage(0, 0); stage(1, BK); stage(2, 2*BK);
    const int NT = HID/BK;   // 32, even
    for (int j=0; j<NT; j+=2){
        CP_WAIT1;
        __syncthreads();
        int k3 = j+3, k4 = j+4;
        if (k3 < NT) stage(k3%NSTG, k3*BK); else CP_COMMIT;
        if (k4 < NT) stage(k4%NSTG, k4*BK); else CP_COMMIT;
        #pragma unroll
        for (int h=0; h<2; h++){
            int s = (j+h)%NSTG;
            uint32_t aoff = sA + (uint32_t)(s*G1_ASTG)*2;
            uint32_t boff = sB + (uint32_t)(s*G1_BSTG)*2;
            #pragma unroll
            for (int ks=0; ks<2; ks++){
                int kb = ks*16;
                uint32_t a0[4], a1[4];
                LDSM4(a0, aoff + (uint32_t)((wm*32     + lAr)*PITCH + kb + lAk)*2);
                LDSM4(a1, aoff + (uint32_t)((wm*32 +16 + lAr)*PITCH + kb + lAk)*2);
                #pragma unroll
                for (int nq=0;nq<2;nq++){
                    int c0 = wn*32 + nq*16;
                    uint32_t bg[4], bu[4];
                    LDSM4(bg, boff + (uint32_t)((c0    + lBr)*PITCH + kb + lBk)*2);
                    LDSM4(bu, boff + (uint32_t)((c0+64 + lBr)*PITCH + kb + lBk)*2);
                    MMA_F16(cg[0][nq*2+0], a0, bg+0);
                    MMA_F16(cg[0][nq*2+1], a0, bg+2);
                    MMA_F16(cg[1][nq*2+0], a1, bg+0);
                    MMA_F16(cg[1][nq*2+1], a1, bg+2);
                    MMA_F16(cu[0][nq*2+0], a0, bu+0);
                    MMA_F16(cu[0][nq*2+1], a0, bu+2);
                    MMA_F16(cu[1][nq*2+0], a1, bu+0);
                    MMA_F16(cu[1][nq*2+1], a1, bu+2);
                }
            }
        }
    }
    int g8 = lane>>2, tg = lane&3;
    #pragma unroll
    for (int mi=0;mi<2;mi++)
        #pragma unroll
        for (int ni=0;ni<4;ni++)
            #pragma unroll
            for (int rr=0;rr<2;rr++){
                int row = wm*32 + mi*16 + g8 + rr*8;
                int col = wn*32 + ni*8 + 2*tg;
                float g0 = cg[mi][ni][rr*2+0], u0 = cu[mi][ni][rr*2+0];
                float g1 = cg[mi][ni][rr*2+1], u1 = cu[mi][ni][rr*2+1];
                float v0 = u0 * (g0 / (1.f + expf(-g0)));
                float v1 = u1 * (g1 / (1.f + expf(-g1)));
                *(__half2*)(g_interh + (size_t)(slot0+row)*INTERN + n0 + col)
                    = __floats2half2_rn(v0, v1);
            }
}

// ============ GEMM2: grid (n-blocks fast, tiles slow), red.v2 combine =========
#define G2_ASTG (BM*PITCH)                 // 5120 halves
#define G2_BSTG (128*PITCH)                // 5120 halves
#define G2_SMEM ((G2_ASTG+G2_BSTG)*NSTG*2) // 102400 bytes

__global__ void __launch_bounds__(256,2) k_gemm2(float* __restrict__ out){
    extern __shared__ __half smh[];
    TileInfo ti = resolve_tile(blockIdx.y);          // tile on y (slow axis)
    if (ti.e < 0) return;
    int slot0 = ti.slot0;
    int n0 = blockIdx.x*128;                         // n-block on x (fast axis)
    int tid=threadIdx.x, lane=tid&31, warp=tid>>5;
    int wm = warp>>1, wn = warp&1;
    uint32_t sA = s2u(smh);
    uint32_t sB = sA + NSTG*G2_ASTG*2;

    int lAr = lane & 15,              lAk = 8*(lane>>4);
    int lBr = (lane&7) + 8*(lane>>4), lBk = 8*((lane>>3)&1);

    int arow = tid>>1, ak = (tid&1)*16;
    const __half* asrc = g_interh + (size_t)(slot0+arow)*INTERN + ak;
    int brow = tid>>1, bk = (tid&1)*16;
    const __half* bsrc = g_wdT + (size_t)ti.e*HID*INTERN + (size_t)(n0+brow)*INTERN + bk;

    float cc[2][8][4];
    #pragma unroll
    for (int i=0;i<2;i++)
        #pragma unroll
        for (int j=0;j<8;j++)
            #pragma unroll
            for (int r=0;r<4;r++) cc[i][j][r]=0.f;

    auto stage = [&](int s, int k0){
        uint32_t ad = sA + (uint32_t)(s*G2_ASTG + arow*PITCH + ak)*2;
        cp16(ad,      asrc + k0,     16);
        cp16(ad + 16, asrc + k0 + 8, 16);
        uint32_t bd = sB + (uint32_t)(s*G2_BSTG + brow*PITCH + bk)*2;
        cp16(bd,      bsrc + k0,     16);
        cp16(bd + 16, bsrc + k0 + 8, 16);
        CP_COMMIT;
    };

    stage(0, 0); stage(1, BK); stage(2, 2*BK);
    const int NT = INTERN/BK;   // 88, even
    for (int j=0; j<NT; j+=2){
        CP_WAIT1;
        __syncthreads();
        int k3 = j+3, k4 = j+4;
        if (k3 < NT) stage(k3%NSTG, k3*BK); else CP_COMMIT;
        if (k4 < NT) stage(k4%NSTG, k4*BK); else CP_COMMIT;
        #pragma unroll
        for (int h=0; h<2; h++){
            int s = (j+h)%NSTG;
            uint32_t aoff = sA + (uint32_t)(s*G2_ASTG)*2;
            uint32_t boff = sB + (uint32_t)(s*G2_BSTG)*2;
            #pragma unroll
            for (int ks=0; ks<2; ks++){
                int kb = ks*16;
                uint32_t a0[4], a1[4];
                LDSM4(a0, aoff + (uint32_t)((wm*32     + lAr)*PITCH + kb + lAk)*2);
                LDSM4(a1, aoff + (uint32_t)((wm*32 +16 + lAr)*PITCH + kb + lAk)*2);
                #pragma unroll
                for (int nq=0;nq<4;nq++){
                    int c0 = wn*64 + nq*16;
                    uint32_t bf[4];
                    LDSM4(bf, boff + (uint32_t)((c0 + lBr)*PITCH + kb + lBk)*2);
                    MMA_F16(cc[0][nq*2+0], a0, bf+0);
                    MMA_F16(cc[0][nq*2+1], a0, bf+2);
                    MMA_F16(cc[1][nq*2+0], a1, bf+0);
                    MMA_F16(cc[1][nq*2+1], a1, bf+2);
                }
            }
        }
    }
    // fused combine via vectorized fire-and-forget reduction:
    // out[token][col..col+1] += w * val2 (still exactly 2 commutative adds/elt)
    int g8 = lane>>2, tg = lane&3;
    #pragma unroll
    for (int mi=0;mi<2;mi++){
        #pragma unroll
        for (int rr=0;rr<2;rr++){
            int row = wm*32 + mi*16 + g8 + rr*8;
            if ((slot0 + row - ti.ebase) >= ti.ecnt) continue;
            int tokn = g_slot_token[slot0+row];
            float w  = g_slot_w[slot0+row];
            float* orow = out + (size_t)tokn*HID + n0;
            #pragma unroll
            for (int nj=0;nj<8;nj++){
                int col = wn*64 + (nj>>1)*16 + (nj&1)*8 + 2*tg;
                REDV2(orow + col, w*cc[mi][nj][rr*2+0], w*cc[mi][nj][rr*2+1]);
            }
        }
    }
}

// ---------------- launch -----------------------------------------------------
extern "C" void kernel_launch(void* const* d_in, const int* in_sizes, int n_in,
                              void* d_out, int out_size){
    const float* x  = (const float*)d_in[0];
    const float* rw = (const float*)d_in[1];
    const float* wg = (const float*)d_in[2];
    const float* wu = (const float*)d_in[3];
    const float* wd = (const float*)d_in[4];
    float* out = (float*)d_out;

    static cudaStream_t s2 = nullptr, s3 = nullptr;
    static cudaEvent_t evR = nullptr, evW = nullptr, evD = nullptr;
    if (!s2){
        cudaStreamCreateWithFlags(&s2, cudaStreamNonBlocking);
        cudaStreamCreateWithFlags(&s3, cudaStreamNonBlocking);
        cudaEventCreateWithFlags(&evR, cudaEventDisableTiming);
        cudaEventCreateWithFlags(&evW, cudaEventDisableTiming);
        cudaEventCreateWithFlags(&evD, cudaEventDisableTiming);
        cudaFuncSetAttribute(k_gemm1, cudaFuncAttributeMaxDynamicSharedMemorySize, G1_SMEM);
        cudaFuncSetAttribute(k_gemm2, cudaFuncAttributeMaxDynamicSharedMemorySize, G2_SMEM);
    }

    void *cntp, *fillp;
    cudaGetSymbolAddress(&cntp,  g_cnt);
    cudaGetSymbolAddress(&fillp, g_fill);
    cudaMemsetAsync(cntp,  0, NEXP*sizeof(int), 0);
    cudaMemsetAsync(fillp, 0, NEXP*sizeof(int), 0);

    // fork: weight conversions on side streams; out-zeroing rides s3
    cudaEventRecord(evR, 0);
    cudaStreamWaitEvent(s2, evR, 0);
    cudaStreamWaitEvent(s3, evR, 0);
    k_wgu<<<dim3(88, 16, 16), dim3(32,8), 0, s2>>>(wg, wu);
    cudaEventRecord(evW, s2);
    cudaMemsetAsync(out, 0, (size_t)out_size*sizeof(float), s3);
    k_wd<<<dim3(88, 16, 8), dim3(32,8), 0, s3>>>(wd);
    cudaEventRecord(evD, s3);

    // main stream: routing chain (concurrent with weight conversion)
    k_router<<<T_TOK/8, 256>>>(x, rw);
    k_scatter<<<(T_TOK+255)/256, 256>>>();

    // join: gemm1 needs wg/wu; gemm2 additionally needs wd + zeroed out
    cudaStreamWaitEvent(0, evW, 0);
    k_gemm1<<<dim3(MAXTILES, INTERN/64), 256, G1_SMEM>>>();
    cudaStreamWaitEvent(0, evD, 0);
    k_gemm2<<<dim3(HID/128, MAXTILES), 256, G2_SMEM>>>(out);
}